// round 1
// baseline (speedup 1.0000x reference)
#include <cuda_runtime.h>
#include <cstdint>
#include <cstddef>

#define D_MODEL 1024
#define NHEAD   16
#define DKH     64
#define BATCH   8
#define SEQ     1024
#define MROWS   (BATCH * SEQ)   // 8192

// ---------------- scratch (device globals: no cudaMalloc allowed) ----------------
__device__ float g_qh[MROWS * D_MODEL];
__device__ float g_kh[MROWS * D_MODEL];
__device__ float g_vh[MROWS * D_MODEL];
__device__ float g_ctx[MROWS * D_MODEL];
__device__ float g_fc[MROWS * D_MODEL];

// =================================================================================
// GEMM: C[M,N] = A[M,K] @ B[N,K]^T + bias[N]   (both inputs K-contiguous, "NT")
// 128x128 tile, BK=8, 256 threads, 8x8 per-thread microtile.
// =================================================================================
__global__ __launch_bounds__(256) void sgemm_nt_bias(
    const float* __restrict__ A, const float* __restrict__ B,
    const float* __restrict__ bias, float* __restrict__ C,
    int M, int N, int K)
{
    __shared__ float As[8][128];
    __shared__ float Bs[8][128];

    const int tid = threadIdx.x;
    const int bn  = blockIdx.x;   // N tile
    const int bm  = blockIdx.y;   // M tile

    const float* Ab = A + (size_t)bm * 128 * K;
    const float* Bb = B + (size_t)bn * 128 * K;

    const int lr = tid >> 1;          // 0..127
    const int lc = (tid & 1) << 2;    // 0 or 4
    const int tx = tid & 15;
    const int ty = tid >> 4;

    float acc[8][8];
#pragma unroll
    for (int i = 0; i < 8; i++)
#pragma unroll
        for (int j = 0; j < 8; j++) acc[i][j] = 0.f;

    for (int k0 = 0; k0 < K; k0 += 8) {
        float4 a4 = *(const float4*)(Ab + (size_t)lr * K + k0 + lc);
        float4 b4 = *(const float4*)(Bb + (size_t)lr * K + k0 + lc);
        As[lc + 0][lr] = a4.x; As[lc + 1][lr] = a4.y;
        As[lc + 2][lr] = a4.z; As[lc + 3][lr] = a4.w;
        Bs[lc + 0][lr] = b4.x; Bs[lc + 1][lr] = b4.y;
        Bs[lc + 2][lr] = b4.z; Bs[lc + 3][lr] = b4.w;
        __syncthreads();

#pragma unroll
        for (int kk = 0; kk < 8; kk++) {
            float ra[8], rb[8];
            *(float4*)&ra[0] = *(const float4*)&As[kk][ty * 8];
            *(float4*)&ra[4] = *(const float4*)&As[kk][ty * 8 + 4];
            *(float4*)&rb[0] = *(const float4*)&Bs[kk][tx * 8];
            *(float4*)&rb[4] = *(const float4*)&Bs[kk][tx * 8 + 4];
#pragma unroll
            for (int i = 0; i < 8; i++)
#pragma unroll
                for (int j = 0; j < 8; j++)
                    acc[i][j] += ra[i] * rb[j];
        }
        __syncthreads();
    }

    const int row0 = bm * 128 + ty * 8;
    const int col0 = bn * 128 + tx * 8;
#pragma unroll
    for (int i = 0; i < 8; i++) {
#pragma unroll
        for (int j = 0; j < 8; j += 4) {
            float4 o;
            o.x = acc[i][j + 0] + bias[col0 + j + 0];
            o.y = acc[i][j + 1] + bias[col0 + j + 1];
            o.z = acc[i][j + 2] + bias[col0 + j + 2];
            o.w = acc[i][j + 3] + bias[col0 + j + 3];
            *(float4*)(C + (size_t)(row0 + i) * N + col0 + j) = o;
        }
    }
}

// =================================================================================
// Fused attention block: one CTA handles (b, h, 32 query rows).
//   scores (fp32, kept in smem) -> mask -> softmax -> attn write -> PV -> ctx
// smem: Qs[32][68] + Ks/Vs[128][69] + Ps[32][1032]  ~= 172 KB (dynamic)
// =================================================================================
#define BQ     32
#define KT     128
#define QS_LD  68
#define KS_LD  69
#define PS_LD  1032
#define ATTN_SMEM_BYTES ((BQ * QS_LD + KT * KS_LD + BQ * PS_LD) * 4)

__global__ __launch_bounds__(256) void attn_kernel(
    const unsigned char* __restrict__ mask,
    float* __restrict__ attn_out)   // may be nullptr
{
    extern __shared__ float sm[];
    float* Qs = sm;                       // BQ * QS_LD
    float* Ks = Qs + BQ * QS_LD;          // KT * KS_LD (reused as Vs)
    float* Ps = Ks + KT * KS_LD;          // BQ * PS_LD

    const int t  = threadIdx.x;
    const int qt = blockIdx.x;
    const int h  = blockIdx.y;
    const int b  = blockIdx.z;
    const int q0 = qt * BQ;

    // ---- load Q tile [32 x 64] ----
#pragma unroll
    for (int i = 0; i < 2; i++) {
        int idx = t + i * 256;                 // 0..511
        int r  = idx >> 4;
        int d4 = (idx & 15) << 2;
        float4 v = *(const float4*)&g_qh[((size_t)(b * SEQ + q0 + r)) * D_MODEL + h * DKH + d4];
        *(float4*)&Qs[r * QS_LD + d4] = v;
    }
    __syncthreads();

    const int rg = (t >> 5) << 2;   // row base: 0,4,...,28 (constant per warp)
    const int cg = t & 31;          // column lane

    // ---- scores: loop over 8 K-tiles of 128 rows ----
    for (int kt = 0; kt < SEQ / KT; kt++) {
        if (kt) __syncthreads();    // everyone done reading Ks from prev iter
        // load K tile natural [n][d], 128x64
#pragma unroll
        for (int i = 0; i < 8; i++) {
            int idx = t + i * 256;             // 0..2047
            int n  = idx >> 4;
            int d4 = (idx & 15) << 2;
            float4 v = *(const float4*)&g_kh[((size_t)(b * SEQ + kt * KT + n)) * D_MODEL + h * DKH + d4];
            Ks[n * KS_LD + d4 + 0] = v.x;
            Ks[n * KS_LD + d4 + 1] = v.y;
            Ks[n * KS_LD + d4 + 2] = v.z;
            Ks[n * KS_LD + d4 + 3] = v.w;
        }
        __syncthreads();

        float a[4][4];
#pragma unroll
        for (int i = 0; i < 4; i++)
#pragma unroll
            for (int j = 0; j < 4; j++) a[i][j] = 0.f;

#pragma unroll 8
        for (int d = 0; d < DKH; d++) {
            float qv[4], kv[4];
#pragma unroll
            for (int i = 0; i < 4; i++) qv[i] = Qs[(rg + i) * QS_LD + d];
#pragma unroll
            for (int j = 0; j < 4; j++) kv[j] = Ks[(cg + 32 * j) * KS_LD + d];
#pragma unroll
            for (int i = 0; i < 4; i++)
#pragma unroll
                for (int j = 0; j < 4; j++) a[i][j] += qv[i] * kv[j];
        }

        const unsigned char* mbase = mask + ((size_t)b * SEQ + q0) * SEQ + (size_t)kt * KT;
#pragma unroll
        for (int i = 0; i < 4; i++) {
#pragma unroll
            for (int j = 0; j < 4; j++) {
                int c = cg + 32 * j;
                float v = a[i][j] * 0.125f;                 // 1/sqrt(64)
                if (mbase[(size_t)(rg + i) * SEQ + c]) v = -1e9f;
                Ps[(rg + i) * PS_LD + kt * KT + c] = v;
            }
        }
    }
    __syncthreads();

    // ---- row softmax: 8 threads per row ----
    {
        int row = t >> 3, sub = t & 7;
        float* pr = Ps + row * PS_LD;
        float m = -1e30f;
        for (int c = sub; c < SEQ; c += 8) m = fmaxf(m, pr[c]);
#pragma unroll
        for (int o = 4; o > 0; o >>= 1) m = fmaxf(m, __shfl_xor_sync(0xffffffffu, m, o, 8));
        float s = 0.f;
        for (int c = sub; c < SEQ; c += 8) { float e = __expf(pr[c] - m); pr[c] = e; s += e; }
#pragma unroll
        for (int o = 4; o > 0; o >>= 1) s += __shfl_xor_sync(0xffffffffu, s, o, 8);
        float inv = 1.0f / s;
        for (int c = sub; c < SEQ; c += 8) pr[c] *= inv;
    }
    __syncthreads();

    // ---- write attn (coalesced float4) ----
    if (attn_out) {
        float* ab = attn_out + (((size_t)(b * NHEAD + h)) * SEQ + q0) * SEQ;
#pragma unroll
        for (int i = 0; i < 32; i++) {
            int idx = t + i * 256;             // 0..8191 float4s
            int r  = idx >> 8;
            int c4 = (idx & 255) << 2;
            *(float4*)&ab[(size_t)r * SEQ + c4] = *(const float4*)&Ps[r * PS_LD + c4];
        }
    }

    // ---- PV: O[32 x 64] ----
    float o[4][2];
#pragma unroll
    for (int i = 0; i < 4; i++) { o[i][0] = 0.f; o[i][1] = 0.f; }
    const int c0 = t & 31;          // cols c0 and c0+32

    for (int kt = 0; kt < SEQ / KT; kt++) {
        __syncthreads();            // done reading Ks/Vs before overwrite
#pragma unroll
        for (int i = 0; i < 8; i++) {
            int idx = t + i * 256;
            int n  = idx >> 4;
            int d4 = (idx & 15) << 2;
            float4 v = *(const float4*)&g_vh[((size_t)(b * SEQ + kt * KT + n)) * D_MODEL + h * DKH + d4];
            Ks[n * KS_LD + d4 + 0] = v.x;
            Ks[n * KS_LD + d4 + 1] = v.y;
            Ks[n * KS_LD + d4 + 2] = v.z;
            Ks[n * KS_LD + d4 + 3] = v.w;
        }
        __syncthreads();

#pragma unroll 8
        for (int n = 0; n < KT; n++) {
            float v0 = Ks[n * KS_LD + c0];
            float v1 = Ks[n * KS_LD + c0 + 32];
#pragma unroll
            for (int i = 0; i < 4; i++) {
                float p = Ps[(rg + i) * PS_LD + kt * KT + n];
                o[i][0] += p * v0;
                o[i][1] += p * v1;
            }
        }
    }

#pragma unroll
    for (int i = 0; i < 4; i++) {
        float* dst = &g_ctx[((size_t)(b * SEQ + q0 + rg + i)) * D_MODEL + h * DKH];
        dst[c0]      = o[i][0];
        dst[c0 + 32] = o[i][1];
    }
}

// =================================================================================
// Residual add + LayerNorm: one CTA per row.
// =================================================================================
__global__ __launch_bounds__(256) void ln_kernel(
    const float* __restrict__ fc, const float* __restrict__ resid,
    const float* __restrict__ gamma, const float* __restrict__ beta,
    float* __restrict__ out)
{
    __shared__ float xs[D_MODEL];
    __shared__ float rs[8], rss[8];

    const int row = blockIdx.x;
    const int t   = threadIdx.x;
    const float* f = fc    + (size_t)row * D_MODEL;
    const float* r = resid + (size_t)row * D_MODEL;

    float s = 0.f, ss = 0.f;
    for (int i = t; i < D_MODEL; i += 256) {
        float x = f[i] + r[i];
        xs[i] = x;
        s += x; ss += x * x;
    }
#pragma unroll
    for (int o = 16; o > 0; o >>= 1) {
        s  += __shfl_xor_sync(0xffffffffu, s, o);
        ss += __shfl_xor_sync(0xffffffffu, ss, o);
    }
    int w = t >> 5, lane = t & 31;
    if (lane == 0) { rs[w] = s; rss[w] = ss; }
    __syncthreads();
    float ts = 0.f, tss = 0.f;
#pragma unroll
    for (int i = 0; i < 8; i++) { ts += rs[i]; tss += rss[i]; }
    float mu  = ts * (1.0f / D_MODEL);
    float var = tss * (1.0f / D_MODEL) - mu * mu;
    float k   = rsqrtf(var + 1e-5f);

    for (int i = t; i < D_MODEL; i += 256)
        out[(size_t)row * D_MODEL + i] = (xs[i] - mu) * k * gamma[i] + beta[i];
}

// =================================================================================
// launch
// =================================================================================
extern "C" void kernel_launch(void* const* d_in, const int* in_sizes, int n_in,
                              void* d_out, int out_size)
{
    const float* q    = (const float*)d_in[0];
    const float* k    = (const float*)d_in[1];
    const float* v    = (const float*)d_in[2];
    const unsigned char* mask = (const unsigned char*)d_in[3];
    const float* w_q  = (const float*)d_in[4];
    const float* b_q  = (const float*)d_in[5];
    const float* w_k  = (const float*)d_in[6];
    const float* b_k  = (const float*)d_in[7];
    const float* w_v  = (const float*)d_in[8];
    const float* b_v  = (const float*)d_in[9];
    const float* w_fc = (const float*)d_in[10];
    const float* b_fc = (const float*)d_in[11];
    const float* ln_g = (const float*)d_in[12];
    const float* ln_b = (const float*)d_in[13];
    float* out = (float*)d_out;

    float *qh, *kh, *vh, *ctx, *fc;
    cudaGetSymbolAddress((void**)&qh,  g_qh);
    cudaGetSymbolAddress((void**)&kh,  g_kh);
    cudaGetSymbolAddress((void**)&vh,  g_vh);
    cudaGetSymbolAddress((void**)&ctx, g_ctx);
    cudaGetSymbolAddress((void**)&fc,  g_fc);

    // Output layout: reference returns (x, attn).
    const long long xe = (long long)MROWS * D_MODEL;                 // 8388608
    const long long ae = (long long)BATCH * NHEAD * SEQ * SEQ;       // 134217728
    float* attn_out = nullptr;
    float* x_out    = out;
    if ((long long)out_size >= xe + ae) {
        attn_out = out + xe;                 // [x | attn]
    } else if ((long long)out_size == ae) {
        attn_out = out;                      // attn-only (unlikely)
        x_out = nullptr;
    }

    dim3 gb(256);
    dim3 gg(D_MODEL / 128, MROWS / 128);

    sgemm_nt_bias<<<gg, gb>>>(q, w_q, b_q, qh, MROWS, D_MODEL, D_MODEL);
    sgemm_nt_bias<<<gg, gb>>>(k, w_k, b_k, kh, MROWS, D_MODEL, D_MODEL);
    sgemm_nt_bias<<<gg, gb>>>(v, w_v, b_v, vh, MROWS, D_MODEL, D_MODEL);

    cudaFuncSetAttribute(attn_kernel, cudaFuncAttributeMaxDynamicSharedMemorySize,
                         ATTN_SMEM_BYTES);
    dim3 ag(SEQ / BQ, NHEAD, BATCH);
    attn_kernel<<<ag, gb, ATTN_SMEM_BYTES>>>(mask, attn_out);

    sgemm_nt_bias<<<gg, gb>>>(ctx, w_fc, b_fc, fc, MROWS, D_MODEL, D_MODEL);

    if (x_out)
        ln_kernel<<<MROWS, gb>>>(fc, q, ln_g, ln_b, x_out);
}

// round 3
// speedup vs baseline: 1.1246x; 1.1246x over previous
#include <cuda_runtime.h>
#include <cstdint>
#include <cstddef>

#define D_MODEL 1024
#define NHEAD   16
#define DKH     64
#define BATCH   8
#define SEQ     1024
#define MROWS   (BATCH * SEQ)   // 8192

// ---------------- scratch (device globals: no cudaMalloc allowed) ----------------
__device__ float g_qh[MROWS * D_MODEL];
__device__ float g_kh[MROWS * D_MODEL];
__device__ float g_vh[MROWS * D_MODEL];
__device__ float g_ctx[MROWS * D_MODEL];
__device__ float g_fc[MROWS * D_MODEL];

// =================================================================================
// tf32 helpers
// =================================================================================
__device__ __forceinline__ uint32_t f2tf32(float x) {
    uint32_t r;
    asm("cvt.rna.tf32.f32 %0, %1;" : "=r"(r) : "f"(x));
    return r;
}
// split x into hi (tf32) + lo (tf32 of residual); residual error ~2^-22
__device__ __forceinline__ void tf32_split(float x, uint32_t& hi, uint32_t& lo) {
    hi = f2tf32(x);
    float hf = __uint_as_float(hi);     // tf32 bit pattern is a valid fp32
    lo = f2tf32(x - hf);
}
__device__ __forceinline__ void mma_tf32(float* c, const uint32_t* a, const uint32_t* b) {
    asm volatile(
        "mma.sync.aligned.m16n8k8.row.col.f32.tf32.tf32.f32 "
        "{%0,%1,%2,%3}, {%4,%5,%6,%7}, {%8,%9}, {%0,%1,%2,%3};"
        : "+f"(c[0]), "+f"(c[1]), "+f"(c[2]), "+f"(c[3])
        : "r"(a[0]), "r"(a[1]), "r"(a[2]), "r"(a[3]), "r"(b[0]), "r"(b[1]));
}

// =================================================================================
// GEMM: C[M,1024] = A[M,1024] @ W[1024,1024]^T + bias    (fp32 in/out)
// tf32 split-2 (3 mma passes, fp32-class accuracy).
// CTA: 128x128, 256 threads (8 warps, each 32 rows x 64 cols).
// K-chunk 16, smem [k][row] LD=136 (conflict-free fragment loads).
// =================================================================================
#define KC     16
#define SLD    136

__global__ __launch_bounds__(256) void gemm_tf32x2(
    const float* __restrict__ A, const float* __restrict__ W,
    const float* __restrict__ bias, float* __restrict__ C)
{
    __shared__ float As[KC][SLD];
    __shared__ float Bs[KC][SLD];

    const int tid = threadIdx.x;
    const int wid = tid >> 5;
    const int lane = tid & 31;
    const int bn = blockIdx.x;            // 8
    const int bm = blockIdx.y;            // M/128
    const int wr = (wid & 3) * 32;        // warp row offset in tile
    const int wc = (wid >> 2) * 64;       // warp col offset in tile

    const int qr  = lane >> 2;            // 0..7
    const int qk  = lane & 3;             // 0..3

    float acc[2][8][4];
#pragma unroll
    for (int i = 0; i < 2; i++)
#pragma unroll
        for (int j = 0; j < 8; j++)
#pragma unroll
            for (int v = 0; v < 4; v++) acc[i][j][v] = 0.f;

    // per-thread load slots: 2 float4 of A, 2 of B per chunk
    const int lrow0 = tid >> 2;           // 0..63   (idx = tid)
    const int lkq0  = tid & 3;
    const int lrow1 = (tid + 256) >> 2;   // 64..127
    const int lkq1  = lkq0;

    const float* Arow0 = A + (size_t)(bm * 128 + lrow0) * D_MODEL + lkq0 * 4;
    const float* Arow1 = A + (size_t)(bm * 128 + lrow1) * D_MODEL + lkq1 * 4;
    const float* Wrow0 = W + (size_t)(bn * 128 + lrow0) * D_MODEL + lkq0 * 4;
    const float* Wrow1 = W + (size_t)(bn * 128 + lrow1) * D_MODEL + lkq1 * 4;

    float4 pa0 = *(const float4*)(Arow0);
    float4 pa1 = *(const float4*)(Arow1);
    float4 pb0 = *(const float4*)(Wrow0);
    float4 pb1 = *(const float4*)(Wrow1);

    for (int c = 0; c < D_MODEL / KC; c++) {
        // stage current prefetch into smem
        As[lkq0 * 4 + 0][lrow0] = pa0.x; As[lkq0 * 4 + 1][lrow0] = pa0.y;
        As[lkq0 * 4 + 2][lrow0] = pa0.z; As[lkq0 * 4 + 3][lrow0] = pa0.w;
        As[lkq1 * 4 + 0][lrow1] = pa1.x; As[lkq1 * 4 + 1][lrow1] = pa1.y;
        As[lkq1 * 4 + 2][lrow1] = pa1.z; As[lkq1 * 4 + 3][lrow1] = pa1.w;
        Bs[lkq0 * 4 + 0][lrow0] = pb0.x; Bs[lkq0 * 4 + 1][lrow0] = pb0.y;
        Bs[lkq0 * 4 + 2][lrow0] = pb0.z; Bs[lkq0 * 4 + 3][lrow0] = pb0.w;
        Bs[lkq1 * 4 + 0][lrow1] = pb1.x; Bs[lkq1 * 4 + 1][lrow1] = pb1.y;
        Bs[lkq1 * 4 + 2][lrow1] = pb1.z; Bs[lkq1 * 4 + 3][lrow1] = pb1.w;
        __syncthreads();

        if (c + 1 < D_MODEL / KC) {
            int koff = (c + 1) * KC;
            pa0 = *(const float4*)(Arow0 + koff);
            pa1 = *(const float4*)(Arow1 + koff);
            pb0 = *(const float4*)(Wrow0 + koff);
            pb1 = *(const float4*)(Wrow1 + koff);
        }

#pragma unroll
        for (int kb = 0; kb < KC; kb += 8) {
            // A fragments (2 m-tiles), split hi/lo
            uint32_t ah[2][4], al[2][4];
#pragma unroll
            for (int mt = 0; mt < 2; mt++) {
                int r0 = wr + mt * 16 + qr;
                tf32_split(As[kb + qk    ][r0    ], ah[mt][0], al[mt][0]);
                tf32_split(As[kb + qk    ][r0 + 8], ah[mt][1], al[mt][1]);
                tf32_split(As[kb + qk + 4][r0    ], ah[mt][2], al[mt][2]);
                tf32_split(As[kb + qk + 4][r0 + 8], ah[mt][3], al[mt][3]);
            }
            // B fragments (8 n-tiles), split hi/lo
            uint32_t bh[8][2], bl[8][2];
#pragma unroll
            for (int nt = 0; nt < 8; nt++) {
                int col = wc + nt * 8 + qr;
                tf32_split(Bs[kb + qk    ][col], bh[nt][0], bl[nt][0]);
                tf32_split(Bs[kb + qk + 4][col], bh[nt][1], bl[nt][1]);
            }
#pragma unroll
            for (int mt = 0; mt < 2; mt++)
#pragma unroll
                for (int nt = 0; nt < 8; nt++) {
                    mma_tf32(acc[mt][nt], ah[mt], bh[nt]);
                    mma_tf32(acc[mt][nt], ah[mt], bl[nt]);
                    mma_tf32(acc[mt][nt], al[mt], bh[nt]);
                }
        }
        __syncthreads();
    }

    // epilogue
#pragma unroll
    for (int mt = 0; mt < 2; mt++) {
        int row0 = bm * 128 + wr + mt * 16 + qr;
#pragma unroll
        for (int nt = 0; nt < 8; nt++) {
            int col = bn * 128 + wc + nt * 8 + (lane & 3) * 2;
            float2 v0, v1;
            v0.x = acc[mt][nt][0] + bias[col];
            v0.y = acc[mt][nt][1] + bias[col + 1];
            v1.x = acc[mt][nt][2] + bias[col];
            v1.y = acc[mt][nt][3] + bias[col + 1];
            *(float2*)(C + (size_t)row0 * D_MODEL + col)       = v0;
            *(float2*)(C + (size_t)(row0 + 8) * D_MODEL + col) = v1;
        }
    }
}

// =================================================================================
// Fused attention block (fp32, from round 1)
// =================================================================================
#define BQ     32
#define KT     128
#define QS_LD  68
#define KS_LD  69
#define PS_LD  1032
#define ATTN_SMEM_BYTES ((BQ * QS_LD + KT * KS_LD + BQ * PS_LD) * 4)

__global__ __launch_bounds__(256) void attn_kernel(
    const unsigned char* __restrict__ mask,
    float* __restrict__ attn_out)
{
    extern __shared__ float smf[];
    float* Qs = smf;
    float* Ks = Qs + BQ * QS_LD;
    float* Ps = Ks + KT * KS_LD;

    const int t  = threadIdx.x;
    const int qt = blockIdx.x;
    const int h  = blockIdx.y;
    const int b  = blockIdx.z;
    const int q0 = qt * BQ;

#pragma unroll
    for (int i = 0; i < 2; i++) {
        int idx = t + i * 256;
        int r  = idx >> 4;
        int d4 = (idx & 15) << 2;
        float4 v = *(const float4*)&g_qh[((size_t)(b * SEQ + q0 + r)) * D_MODEL + h * DKH + d4];
        *(float4*)&Qs[r * QS_LD + d4] = v;
    }
    __syncthreads();

    const int rg = (t >> 5) << 2;
    const int cg = t & 31;

    for (int kt = 0; kt < SEQ / KT; kt++) {
        if (kt) __syncthreads();
#pragma unroll
        for (int i = 0; i < 8; i++) {
            int idx = t + i * 256;
            int n  = idx >> 4;
            int d4 = (idx & 15) << 2;
            float4 v = *(const float4*)&g_kh[((size_t)(b * SEQ + kt * KT + n)) * D_MODEL + h * DKH + d4];
            Ks[n * KS_LD + d4 + 0] = v.x;
            Ks[n * KS_LD + d4 + 1] = v.y;
            Ks[n * KS_LD + d4 + 2] = v.z;
            Ks[n * KS_LD + d4 + 3] = v.w;
        }
        __syncthreads();

        float a[4][4];
#pragma unroll
        for (int i = 0; i < 4; i++)
#pragma unroll
            for (int j = 0; j < 4; j++) a[i][j] = 0.f;

#pragma unroll 8
        for (int d = 0; d < DKH; d++) {
            float qv[4], kv[4];
#pragma unroll
            for (int i = 0; i < 4; i++) qv[i] = Qs[(rg + i) * QS_LD + d];
#pragma unroll
            for (int j = 0; j < 4; j++) kv[j] = Ks[(cg + 32 * j) * KS_LD + d];
#pragma unroll
            for (int i = 0; i < 4; i++)
#pragma unroll
                for (int j = 0; j < 4; j++) a[i][j] += qv[i] * kv[j];
        }

        const unsigned char* mbase = mask + ((size_t)b * SEQ + q0) * SEQ + (size_t)kt * KT;
#pragma unroll
        for (int i = 0; i < 4; i++) {
#pragma unroll
            for (int j = 0; j < 4; j++) {
                int cc = cg + 32 * j;
                float v = a[i][j] * 0.125f;
                if (mbase[(size_t)(rg + i) * SEQ + cc]) v = -1e9f;
                Ps[(rg + i) * PS_LD + kt * KT + cc] = v;
            }
        }
    }
    __syncthreads();

    {
        int row = t >> 3, sub = t & 7;
        float* pr = Ps + row * PS_LD;
        float m = -1e30f;
        for (int cc = sub; cc < SEQ; cc += 8) m = fmaxf(m, pr[cc]);
#pragma unroll
        for (int o = 4; o > 0; o >>= 1) m = fmaxf(m, __shfl_xor_sync(0xffffffffu, m, o, 8));
        float s = 0.f;
        for (int cc = sub; cc < SEQ; cc += 8) { float e = __expf(pr[cc] - m); pr[cc] = e; s += e; }
#pragma unroll
        for (int o = 4; o > 0; o >>= 1) s += __shfl_xor_sync(0xffffffffu, s, o, 8);
        float inv = 1.0f / s;
        for (int cc = sub; cc < SEQ; cc += 8) pr[cc] *= inv;
    }
    __syncthreads();

    if (attn_out) {
        float* ab = attn_out + (((size_t)(b * NHEAD + h)) * SEQ + q0) * SEQ;
#pragma unroll
        for (int i = 0; i < 32; i++) {
            int idx = t + i * 256;
            int r  = idx >> 8;
            int c4 = (idx & 255) << 2;
            *(float4*)&ab[(size_t)r * SEQ + c4] = *(const float4*)&Ps[r * PS_LD + c4];
        }
    }

    float o[4][2];
#pragma unroll
    for (int i = 0; i < 4; i++) { o[i][0] = 0.f; o[i][1] = 0.f; }
    const int c0 = t & 31;

    for (int kt = 0; kt < SEQ / KT; kt++) {
        __syncthreads();
#pragma unroll
        for (int i = 0; i < 8; i++) {
            int idx = t + i * 256;
            int n  = idx >> 4;
            int d4 = (idx & 15) << 2;
            float4 v = *(const float4*)&g_vh[((size_t)(b * SEQ + kt * KT + n)) * D_MODEL + h * DKH + d4];
            Ks[n * KS_LD + d4 + 0] = v.x;
            Ks[n * KS_LD + d4 + 1] = v.y;
            Ks[n * KS_LD + d4 + 2] = v.z;
            Ks[n * KS_LD + d4 + 3] = v.w;
        }
        __syncthreads();

#pragma unroll 8
        for (int n = 0; n < KT; n++) {
            float v0 = Ks[n * KS_LD + c0];
            float v1 = Ks[n * KS_LD + c0 + 32];
#pragma unroll
            for (int i = 0; i < 4; i++) {
                float p = Ps[(rg + i) * PS_LD + kt * KT + n];
                o[i][0] += p * v0;
                o[i][1] += p * v1;
            }
        }
    }

#pragma unroll
    for (int i = 0; i < 4; i++) {
        float* dst = &g_ctx[((size_t)(b * SEQ + q0 + rg + i)) * D_MODEL + h * DKH];
        dst[c0]      = o[i][0];
        dst[c0 + 32] = o[i][1];
    }
}

// =================================================================================
// Residual add + LayerNorm
// =================================================================================
__global__ __launch_bounds__(256) void ln_kernel(
    const float* __restrict__ fc, const float* __restrict__ resid,
    const float* __restrict__ gamma, const float* __restrict__ beta,
    float* __restrict__ out)
{
    __shared__ float xs[D_MODEL];
    __shared__ float rs[8], rss[8];

    const int row = blockIdx.x;
    const int t   = threadIdx.x;
    const float* f = fc    + (size_t)row * D_MODEL;
    const float* r = resid + (size_t)row * D_MODEL;

    float s = 0.f, ss = 0.f;
    for (int i = t; i < D_MODEL; i += 256) {
        float x = f[i] + r[i];
        xs[i] = x;
        s += x; ss += x * x;
    }
#pragma unroll
    for (int o = 16; o > 0; o >>= 1) {
        s  += __shfl_xor_sync(0xffffffffu, s, o);
        ss += __shfl_xor_sync(0xffffffffu, ss, o);
    }
    int w = t >> 5, lane = t & 31;
    if (lane == 0) { rs[w] = s; rss[w] = ss; }
    __syncthreads();
    float ts = 0.f, tss = 0.f;
#pragma unroll
    for (int i = 0; i < 8; i++) { ts += rs[i]; tss += rss[i]; }
    float mu  = ts * (1.0f / D_MODEL);
    float var = tss * (1.0f / D_MODEL) - mu * mu;
    float kk  = rsqrtf(var + 1e-5f);

    for (int i = t; i < D_MODEL; i += 256)
        out[(size_t)row * D_MODEL + i] = (xs[i] - mu) * kk * gamma[i] + beta[i];
}

// =================================================================================
// launch
// =================================================================================
extern "C" void kernel_launch(void* const* d_in, const int* in_sizes, int n_in,
                              void* d_out, int out_size)
{
    const float* q    = (const float*)d_in[0];
    const float* k    = (const float*)d_in[1];
    const float* v    = (const float*)d_in[2];
    const unsigned char* mask = (const unsigned char*)d_in[3];
    const float* w_q  = (const float*)d_in[4];
    const float* b_q  = (const float*)d_in[5];
    const float* w_k  = (const float*)d_in[6];
    const float* b_k  = (const float*)d_in[7];
    const float* w_v  = (const float*)d_in[8];
    const float* b_v  = (const float*)d_in[9];
    const float* w_fc = (const float*)d_in[10];
    const float* b_fc = (const float*)d_in[11];
    const float* ln_g = (const float*)d_in[12];
    const float* ln_b = (const float*)d_in[13];
    float* out = (float*)d_out;

    float *qh, *kh, *vh, *ctx, *fc;
    cudaGetSymbolAddress((void**)&qh,  g_qh);
    cudaGetSymbolAddress((void**)&kh,  g_kh);
    cudaGetSymbolAddress((void**)&vh,  g_vh);
    cudaGetSymbolAddress((void**)&ctx, g_ctx);
    cudaGetSymbolAddress((void**)&fc,  g_fc);

    const long long xe = (long long)MROWS * D_MODEL;
    const long long ae = (long long)BATCH * NHEAD * SEQ * SEQ;
    float* attn_out = nullptr;
    float* x_out    = out;
    if ((long long)out_size >= xe + ae) {
        attn_out = out + xe;
    } else if ((long long)out_size == ae) {
        attn_out = out;
        x_out = nullptr;
    }

    cudaFuncSetAttribute(attn_kernel, cudaFuncAttributeMaxDynamicSharedMemorySize,
                         ATTN_SMEM_BYTES);

    dim3 gb(256);
    dim3 gg(D_MODEL / 128, MROWS / 128);    // (8, 64)

    gemm_tf32x2<<<gg, gb>>>(q, w_q, b_q, qh);
    gemm_tf32x2<<<gg, gb>>>(k, w_k, b_k, kh);
    gemm_tf32x2<<<gg, gb>>>(v, w_v, b_v, vh);

    dim3 ag(SEQ / BQ, NHEAD, BATCH);
    attn_kernel<<<ag, gb, ATTN_SMEM_BYTES>>>(mask, attn_out);

    gemm_tf32x2<<<gg, gb>>>(ctx, w_fc, b_fc, fc);

    if (x_out)
        ln_kernel<<<MROWS, gb>>>(fc, q, ln_g, ln_b, x_out);
}

// round 4
// speedup vs baseline: 1.3074x; 1.1625x over previous
#include <cuda_runtime.h>
#include <cuda_bf16.h>
#include <cstdint>
#include <cstddef>

#define D_MODEL 1024
#define NHEAD   16
#define DKH     64
#define BATCH   8
#define SEQ     1024
#define MROWS   (BATCH * SEQ)   // 8192

// ---------------- scratch (device globals: no cudaMalloc allowed) ----------------
__device__ float g_qh[MROWS * D_MODEL];
__device__ float g_kh[MROWS * D_MODEL];
__device__ float g_vh[MROWS * D_MODEL];
__device__ float g_ctx[MROWS * D_MODEL];
__device__ float g_fc[MROWS * D_MODEL];
// bf16 3-level split operands
__device__ __align__(16) unsigned short g_a0[MROWS * D_MODEL];
__device__ __align__(16) unsigned short g_a1[MROWS * D_MODEL];
__device__ __align__(16) unsigned short g_a2[MROWS * D_MODEL];
__device__ __align__(16) unsigned short g_b0[D_MODEL * D_MODEL];
__device__ __align__(16) unsigned short g_b1[D_MODEL * D_MODEL];
__device__ __align__(16) unsigned short g_b2[D_MODEL * D_MODEL];

// =================================================================================
// helpers
// =================================================================================
__device__ __forceinline__ uint32_t smem_u32(const void* p) {
    uint32_t a;
    asm("{ .reg .u64 t; cvta.to.shared.u64 t, %1; cvt.u32.u64 %0, t; }" : "=r"(a) : "l"(p));
    return a;
}
__device__ __forceinline__ void ldsm_x4(uint32_t* r, uint32_t addr) {
    asm volatile("ldmatrix.sync.aligned.m8n8.x4.shared.b16 {%0,%1,%2,%3}, [%4];"
        : "=r"(r[0]), "=r"(r[1]), "=r"(r[2]), "=r"(r[3]) : "r"(addr));
}
__device__ __forceinline__ void mma_bf16(float* c, const uint32_t* a, const uint32_t* b) {
    asm volatile("mma.sync.aligned.m16n8k16.row.col.f32.bf16.bf16.f32 "
        "{%0,%1,%2,%3}, {%4,%5,%6,%7}, {%8,%9}, {%0,%1,%2,%3};"
        : "+f"(c[0]), "+f"(c[1]), "+f"(c[2]), "+f"(c[3])
        : "r"(a[0]), "r"(a[1]), "r"(a[2]), "r"(a[3]), "r"(b[0]), "r"(b[1]));
}
__device__ __forceinline__ void cp16(uint32_t dst, const void* src) {
    asm volatile("cp.async.cg.shared.global [%0], [%1], 16;" :: "r"(dst), "l"(src));
}

// =================================================================================
// fp32 -> bf16 3-level split: x = h + m + l + O(2^-25 x)   (residuals exact in fp32)
// =================================================================================
__global__ __launch_bounds__(256) void split3_kernel(
    const float* __restrict__ x, unsigned short* __restrict__ h,
    unsigned short* __restrict__ m, unsigned short* __restrict__ l, int n4)
{
    int i = blockIdx.x * 256 + threadIdx.x;
    if (i >= n4) return;
    float4 v = ((const float4*)x)[i];
    float vv[4] = { v.x, v.y, v.z, v.w };
    unsigned short hh[4], mm[4], ll[4];
#pragma unroll
    for (int j = 0; j < 4; j++) {
        __nv_bfloat16 hb = __float2bfloat16(vv[j]);
        float r1 = vv[j] - __bfloat162float(hb);
        __nv_bfloat16 mb = __float2bfloat16(r1);
        float r2 = r1 - __bfloat162float(mb);
        __nv_bfloat16 lb = __float2bfloat16(r2);
        hh[j] = __bfloat16_as_ushort(hb);
        mm[j] = __bfloat16_as_ushort(mb);
        ll[j] = __bfloat16_as_ushort(lb);
    }
    ((ushort4*)h)[i] = make_ushort4(hh[0], hh[1], hh[2], hh[3]);
    ((ushort4*)m)[i] = make_ushort4(mm[0], mm[1], mm[2], mm[3]);
    ((ushort4*)l)[i] = make_ushort4(ll[0], ll[1], ll[2], ll[3]);
}

// =================================================================================
// multi-level bf16 mma GEMM:
//   C[M,1024] = sum_passes A_la[M,1024] @ B_lb[1024,1024]^T + bias
// CTA 128x128, 256 thr (8 warps, 32x64 warp tiles), KC=32, cp.async 2-stage,
// ldmatrix fragment loads. NLEV=3/NPASS=6 -> ~2^-25 operand accuracy (Q/K);
// NLEV=2/NPASS=3 -> ~2^-17 (V/FC).
// =================================================================================
#define KC         32
#define NCHUNK     (D_MODEL / KC)       // 32
#define TLD_B      80                    // bytes per smem row (40 bf16, conflict-free)
#define TILE_BYTES (128 * TLD_B)         // 10240

template<int NLEV, int NPASS>
__global__ void __launch_bounds__(256) gemm_ml(
    const unsigned short* __restrict__ A0, const unsigned short* __restrict__ A1,
    const unsigned short* __restrict__ A2,
    const unsigned short* __restrict__ B0, const unsigned short* __restrict__ B1,
    const unsigned short* __restrict__ B2,
    const float* __restrict__ bias, float* __restrict__ C)
{
    extern __shared__ char smc[];
    const uint32_t sbase = smem_u32(smc);
    const int tid = threadIdx.x, wid = tid >> 5, lane = tid & 31;
    const int bn = blockIdx.x, bm = blockIdx.y;
    const int wr = (wid & 3) * 32, wc = (wid >> 2) * 64;

    const unsigned short* srcs[2 * NLEV];
    {
        const size_t ao = (size_t)bm * 128 * D_MODEL;
        const size_t bo = (size_t)bn * 128 * D_MODEL;
        srcs[0] = A0 + ao;
        srcs[1] = A1 + ao;
        if (NLEV == 3) srcs[2] = A2 + ao;
        srcs[NLEV + 0] = B0 + bo;
        srcs[NLEV + 1] = B1 + bo;
        if (NLEV == 3) srcs[NLEV + 2] = B2 + bo;
    }

    float acc[2][8][4];
#pragma unroll
    for (int i = 0; i < 2; i++)
#pragma unroll
        for (int j = 0; j < 8; j++)
#pragma unroll
            for (int v = 0; v < 4; v++) acc[i][j][v] = 0.f;

    // ldmatrix lane addresses (verified conflict-free at 80B row stride)
    const uint32_t a_l = (uint32_t)(wr + (lane & 15)) * TLD_B + ((lane >> 4) & 1) * 16;
    const uint32_t b_l = (uint32_t)(wc + (lane & 7) + ((lane >> 4) & 1) * 8) * TLD_B
                       + ((lane >> 3) & 1) * 16;

    auto fill = [&](int c, int s) {
        const int nunits = NLEV * 2 * 512;           // 16B units per stage
        for (int i = tid; i < nunits; i += 256) {
            int c16 = i & 3;
            int r   = (i >> 2) & 127;
            int ml  = i >> 9;
            const unsigned short* src = srcs[ml] + (size_t)r * D_MODEL + c * KC + c16 * 8;
            uint32_t dst = sbase + (uint32_t)(s * 2 * NLEV + ml) * TILE_BYTES
                         + (uint32_t)r * TLD_B + c16 * 16;
            cp16(dst, src);
        }
        asm volatile("cp.async.commit_group;" ::: "memory");
    };

    fill(0, 0);
    fill(1, 1);

    constexpr int PA[6] = { 0, 0, 1, 0, 1, 2 };
    constexpr int PB[6] = { 0, 1, 0, 2, 1, 0 };

    for (int c = 0; c < NCHUNK; c++) {
        if (c + 1 < NCHUNK)
            asm volatile("cp.async.wait_group 1;" ::: "memory");
        else
            asm volatile("cp.async.wait_group 0;" ::: "memory");
        __syncthreads();

        const int s = c & 1;
        const uint32_t abase = sbase + (uint32_t)(s * 2 * NLEV) * TILE_BYTES;
        const uint32_t bbase = abase + NLEV * TILE_BYTES;

#pragma unroll
        for (int kb = 0; kb < 2; kb++) {
            const uint32_t kbyte = kb * 32;
            uint32_t af[NLEV][2][4];
            uint32_t bfr[NLEV][4][4];
#pragma unroll
            for (int lv = 0; lv < NLEV; lv++) {
#pragma unroll
                for (int mt = 0; mt < 2; mt++)
                    ldsm_x4(af[lv][mt],
                            abase + lv * TILE_BYTES + a_l + mt * (16 * TLD_B) + kbyte);
#pragma unroll
                for (int np = 0; np < 4; np++)
                    ldsm_x4(bfr[lv][np],
                            bbase + lv * TILE_BYTES + b_l + np * (16 * TLD_B) + kbyte);
            }
#pragma unroll
            for (int p = 0; p < NPASS; p++) {
#pragma unroll
                for (int mt = 0; mt < 2; mt++)
#pragma unroll
                    for (int nt = 0; nt < 8; nt++)
                        mma_bf16(acc[mt][nt], af[PA[p]][mt],
                                 &bfr[PB[p]][nt >> 1][(nt & 1) * 2]);
            }
        }
        __syncthreads();
        if (c + 2 < NCHUNK) fill(c + 2, s);
    }

    // epilogue: + bias, fp32 store
    const int qr = lane >> 2;
#pragma unroll
    for (int mt = 0; mt < 2; mt++) {
        int row0 = bm * 128 + wr + mt * 16 + qr;
#pragma unroll
        for (int nt = 0; nt < 8; nt++) {
            int col = bn * 128 + wc + nt * 8 + (lane & 3) * 2;
            float2 v0, v1;
            v0.x = acc[mt][nt][0] + bias[col];
            v0.y = acc[mt][nt][1] + bias[col + 1];
            v1.x = acc[mt][nt][2] + bias[col];
            v1.y = acc[mt][nt][3] + bias[col + 1];
            *(float2*)(C + (size_t)row0 * D_MODEL + col)       = v0;
            *(float2*)(C + (size_t)(row0 + 8) * D_MODEL + col) = v1;
        }
    }
}

// =================================================================================
// Fused attention block (fp32, from round 1)
// =================================================================================
#define BQ     32
#define KT     128
#define QS_LD  68
#define KS_LD  69
#define PS_LD  1032
#define ATTN_SMEM_BYTES ((BQ * QS_LD + KT * KS_LD + BQ * PS_LD) * 4)

__global__ __launch_bounds__(256) void attn_kernel(
    const unsigned char* __restrict__ mask,
    float* __restrict__ attn_out)
{
    extern __shared__ float smf[];
    float* Qs = smf;
    float* Ks = Qs + BQ * QS_LD;
    float* Ps = Ks + KT * KS_LD;

    const int t  = threadIdx.x;
    const int qt = blockIdx.x;
    const int h  = blockIdx.y;
    const int b  = blockIdx.z;
    const int q0 = qt * BQ;

#pragma unroll
    for (int i = 0; i < 2; i++) {
        int idx = t + i * 256;
        int r  = idx >> 4;
        int d4 = (idx & 15) << 2;
        float4 v = *(const float4*)&g_qh[((size_t)(b * SEQ + q0 + r)) * D_MODEL + h * DKH + d4];
        *(float4*)&Qs[r * QS_LD + d4] = v;
    }
    __syncthreads();

    const int rg = (t >> 5) << 2;
    const int cg = t & 31;

    for (int kt = 0; kt < SEQ / KT; kt++) {
        if (kt) __syncthreads();
#pragma unroll
        for (int i = 0; i < 8; i++) {
            int idx = t + i * 256;
            int n  = idx >> 4;
            int d4 = (idx & 15) << 2;
            float4 v = *(const float4*)&g_kh[((size_t)(b * SEQ + kt * KT + n)) * D_MODEL + h * DKH + d4];
            Ks[n * KS_LD + d4 + 0] = v.x;
            Ks[n * KS_LD + d4 + 1] = v.y;
            Ks[n * KS_LD + d4 + 2] = v.z;
            Ks[n * KS_LD + d4 + 3] = v.w;
        }
        __syncthreads();

        float a[4][4];
#pragma unroll
        for (int i = 0; i < 4; i++)
#pragma unroll
            for (int j = 0; j < 4; j++) a[i][j] = 0.f;

#pragma unroll 8
        for (int d = 0; d < DKH; d++) {
            float qv[4], kv[4];
#pragma unroll
            for (int i = 0; i < 4; i++) qv[i] = Qs[(rg + i) * QS_LD + d];
#pragma unroll
            for (int j = 0; j < 4; j++) kv[j] = Ks[(cg + 32 * j) * KS_LD + d];
#pragma unroll
            for (int i = 0; i < 4; i++)
#pragma unroll
                for (int j = 0; j < 4; j++) a[i][j] += qv[i] * kv[j];
        }

        const unsigned char* mbase = mask + ((size_t)b * SEQ + q0) * SEQ + (size_t)kt * KT;
#pragma unroll
        for (int i = 0; i < 4; i++) {
#pragma unroll
            for (int j = 0; j < 4; j++) {
                int cc = cg + 32 * j;
                float v = a[i][j] * 0.125f;
                if (mbase[(size_t)(rg + i) * SEQ + cc]) v = -1e9f;
                Ps[(rg + i) * PS_LD + kt * KT + cc] = v;
            }
        }
    }
    __syncthreads();

    {
        int row = t >> 3, sub = t & 7;
        float* pr = Ps + row * PS_LD;
        float m = -1e30f;
        for (int cc = sub; cc < SEQ; cc += 8) m = fmaxf(m, pr[cc]);
#pragma unroll
        for (int o = 4; o > 0; o >>= 1) m = fmaxf(m, __shfl_xor_sync(0xffffffffu, m, o, 8));
        float s = 0.f;
        for (int cc = sub; cc < SEQ; cc += 8) { float e = __expf(pr[cc] - m); pr[cc] = e; s += e; }
#pragma unroll
        for (int o = 4; o > 0; o >>= 1) s += __shfl_xor_sync(0xffffffffu, s, o, 8);
        float inv = 1.0f / s;
        for (int cc = sub; cc < SEQ; cc += 8) pr[cc] *= inv;
    }
    __syncthreads();

    if (attn_out) {
        float* ab = attn_out + (((size_t)(b * NHEAD + h)) * SEQ + q0) * SEQ;
#pragma unroll
        for (int i = 0; i < 32; i++) {
            int idx = t + i * 256;
            int r  = idx >> 8;
            int c4 = (idx & 255) << 2;
            *(float4*)&ab[(size_t)r * SEQ + c4] = *(const float4*)&Ps[r * PS_LD + c4];
        }
    }

    float o[4][2];
#pragma unroll
    for (int i = 0; i < 4; i++) { o[i][0] = 0.f; o[i][1] = 0.f; }
    const int c0 = t & 31;

    for (int kt = 0; kt < SEQ / KT; kt++) {
        __syncthreads();
#pragma unroll
        for (int i = 0; i < 8; i++) {
            int idx = t + i * 256;
            int n  = idx >> 4;
            int d4 = (idx & 15) << 2;
            float4 v = *(const float4*)&g_vh[((size_t)(b * SEQ + kt * KT + n)) * D_MODEL + h * DKH + d4];
            Ks[n * KS_LD + d4 + 0] = v.x;
            Ks[n * KS_LD + d4 + 1] = v.y;
            Ks[n * KS_LD + d4 + 2] = v.z;
            Ks[n * KS_LD + d4 + 3] = v.w;
        }
        __syncthreads();

#pragma unroll 8
        for (int n = 0; n < KT; n++) {
            float v0 = Ks[n * KS_LD + c0];
            float v1 = Ks[n * KS_LD + c0 + 32];
#pragma unroll
            for (int i = 0; i < 4; i++) {
                float p = Ps[(rg + i) * PS_LD + kt * KT + n];
                o[i][0] += p * v0;
                o[i][1] += p * v1;
            }
        }
    }

#pragma unroll
    for (int i = 0; i < 4; i++) {
        float* dst = &g_ctx[((size_t)(b * SEQ + q0 + rg + i)) * D_MODEL + h * DKH];
        dst[c0]      = o[i][0];
        dst[c0 + 32] = o[i][1];
    }
}

// =================================================================================
// Residual add + LayerNorm
// =================================================================================
__global__ __launch_bounds__(256) void ln_kernel(
    const float* __restrict__ fc, const float* __restrict__ resid,
    const float* __restrict__ gamma, const float* __restrict__ beta,
    float* __restrict__ out)
{
    __shared__ float xs[D_MODEL];
    __shared__ float rs[8], rss[8];

    const int row = blockIdx.x;
    const int t   = threadIdx.x;
    const float* f = fc    + (size_t)row * D_MODEL;
    const float* r = resid + (size_t)row * D_MODEL;

    float s = 0.f, ss = 0.f;
    for (int i = t; i < D_MODEL; i += 256) {
        float x = f[i] + r[i];
        xs[i] = x;
        s += x; ss += x * x;
    }
#pragma unroll
    for (int o = 16; o > 0; o >>= 1) {
        s  += __shfl_xor_sync(0xffffffffu, s, o);
        ss += __shfl_xor_sync(0xffffffffu, ss, o);
    }
    int w = t >> 5, lane = t & 31;
    if (lane == 0) { rs[w] = s; rss[w] = ss; }
    __syncthreads();
    float ts = 0.f, tss = 0.f;
#pragma unroll
    for (int i = 0; i < 8; i++) { ts += rs[i]; tss += rss[i]; }
    float mu  = ts * (1.0f / D_MODEL);
    float var = tss * (1.0f / D_MODEL) - mu * mu;
    float kk  = rsqrtf(var + 1e-5f);

    for (int i = t; i < D_MODEL; i += 256)
        out[(size_t)row * D_MODEL + i] = (xs[i] - mu) * kk * gamma[i] + beta[i];
}

// =================================================================================
// launch
// =================================================================================
extern "C" void kernel_launch(void* const* d_in, const int* in_sizes, int n_in,
                              void* d_out, int out_size)
{
    const float* q    = (const float*)d_in[0];
    const float* k    = (const float*)d_in[1];
    const float* v    = (const float*)d_in[2];
    const unsigned char* mask = (const unsigned char*)d_in[3];
    const float* w_q  = (const float*)d_in[4];
    const float* b_q  = (const float*)d_in[5];
    const float* w_k  = (const float*)d_in[6];
    const float* b_k  = (const float*)d_in[7];
    const float* w_v  = (const float*)d_in[8];
    const float* b_v  = (const float*)d_in[9];
    const float* w_fc = (const float*)d_in[10];
    const float* b_fc = (const float*)d_in[11];
    const float* ln_g = (const float*)d_in[12];
    const float* ln_b = (const float*)d_in[13];
    float* out = (float*)d_out;

    float *qh, *kh, *vh, *ctx, *fc;
    unsigned short *a0, *a1, *a2, *b0, *b1, *b2;
    cudaGetSymbolAddress((void**)&qh,  g_qh);
    cudaGetSymbolAddress((void**)&kh,  g_kh);
    cudaGetSymbolAddress((void**)&vh,  g_vh);
    cudaGetSymbolAddress((void**)&ctx, g_ctx);
    cudaGetSymbolAddress((void**)&fc,  g_fc);
    cudaGetSymbolAddress((void**)&a0,  g_a0);
    cudaGetSymbolAddress((void**)&a1,  g_a1);
    cudaGetSymbolAddress((void**)&a2,  g_a2);
    cudaGetSymbolAddress((void**)&b0,  g_b0);
    cudaGetSymbolAddress((void**)&b1,  g_b1);
    cudaGetSymbolAddress((void**)&b2,  g_b2);

    const long long xe = (long long)MROWS * D_MODEL;
    const long long ae = (long long)BATCH * NHEAD * SEQ * SEQ;
    float* attn_out = nullptr;
    float* x_out    = out;
    if ((long long)out_size >= xe + ae) {
        attn_out = out + xe;
    } else if ((long long)out_size == ae) {
        attn_out = out;
        x_out = nullptr;
    }

    const int SM6 = 2 * 6 * TILE_BYTES;   // 122880
    const int SM3 = 2 * 4 * TILE_BYTES;   // 81920
    cudaFuncSetAttribute(gemm_ml<3, 6>, cudaFuncAttributeMaxDynamicSharedMemorySize, SM6);
    cudaFuncSetAttribute(gemm_ml<2, 3>, cudaFuncAttributeMaxDynamicSharedMemorySize, SM3);
    cudaFuncSetAttribute(attn_kernel, cudaFuncAttributeMaxDynamicSharedMemorySize,
                         ATTN_SMEM_BYTES);

    const int nA4 = MROWS * D_MODEL / 4;
    const int nW4 = D_MODEL * D_MODEL / 4;
    dim3 gb(256);
    dim3 gg(D_MODEL / 128, MROWS / 128);    // (8, 64)

    // Q projection (high precision: 6-pass)
    split3_kernel<<<nA4 / 256, gb>>>(q, a0, a1, a2, nA4);
    split3_kernel<<<nW4 / 256, gb>>>(w_q, b0, b1, b2, nW4);
    gemm_ml<3, 6><<<gg, gb, SM6>>>(a0, a1, a2, b0, b1, b2, b_q, qh);
    // K projection (high precision: 6-pass)
    split3_kernel<<<nA4 / 256, gb>>>(k, a0, a1, a2, nA4);
    split3_kernel<<<nW4 / 256, gb>>>(w_k, b0, b1, b2, nW4);
    gemm_ml<3, 6><<<gg, gb, SM6>>>(a0, a1, a2, b0, b1, b2, b_k, kh);
    // V projection (3-pass)
    split3_kernel<<<nA4 / 256, gb>>>(v, a0, a1, a2, nA4);
    split3_kernel<<<nW4 / 256, gb>>>(w_v, b0, b1, b2, nW4);
    gemm_ml<2, 3><<<gg, gb, SM3>>>(a0, a1, a2, b0, b1, b2, b_v, vh);

    // attention
    dim3 ag(SEQ / BQ, NHEAD, BATCH);
    attn_kernel<<<ag, gb, ATTN_SMEM_BYTES>>>(mask, attn_out);

    // FC (3-pass)
    split3_kernel<<<nA4 / 256, gb>>>(ctx, a0, a1, a2, nA4);
    split3_kernel<<<nW4 / 256, gb>>>(w_fc, b0, b1, b2, nW4);
    gemm_ml<2, 3><<<gg, gb, SM3>>>(a0, a1, a2, b0, b1, b2, b_fc, fc);

    if (x_out)
        ln_kernel<<<MROWS, gb>>>(fc, q, ln_g, ln_b, x_out);
}

// round 5
// speedup vs baseline: 1.4354x; 1.0979x over previous
#include <cuda_runtime.h>
#include <cuda_fp16.h>
#include <cstdint>
#include <cstddef>

#define D_MODEL 1024
#define NHEAD   16
#define DKH     64
#define BATCH   8
#define SEQ     1024
#define MROWS   (BATCH * SEQ)   // 8192

// ---------------- scratch (device globals: no cudaMalloc allowed) ----------------
__device__ float g_qh[MROWS * D_MODEL];
__device__ float g_kh[MROWS * D_MODEL];
__device__ float g_vh[MROWS * D_MODEL];
__device__ float g_ctx[MROWS * D_MODEL];
__device__ float g_fc[MROWS * D_MODEL];
// fp16 2-level split operands
__device__ __align__(16) unsigned short g_a0[MROWS * D_MODEL];
__device__ __align__(16) unsigned short g_a1[MROWS * D_MODEL];
__device__ __align__(16) unsigned short g_b0[D_MODEL * D_MODEL];
__device__ __align__(16) unsigned short g_b1[D_MODEL * D_MODEL];

// =================================================================================
// helpers
// =================================================================================
__device__ __forceinline__ uint32_t smem_u32(const void* p) {
    uint32_t a;
    asm("{ .reg .u64 t; cvta.to.shared.u64 t, %1; cvt.u32.u64 %0, t; }" : "=r"(a) : "l"(p));
    return a;
}
__device__ __forceinline__ void ldsm_x4(uint32_t* r, uint32_t addr) {
    asm volatile("ldmatrix.sync.aligned.m8n8.x4.shared.b16 {%0,%1,%2,%3}, [%4];"
        : "=r"(r[0]), "=r"(r[1]), "=r"(r[2]), "=r"(r[3]) : "r"(addr));
}
__device__ __forceinline__ void mma_f16(float* c, const uint32_t* a, const uint32_t* b) {
    asm volatile("mma.sync.aligned.m16n8k16.row.col.f32.f16.f16.f32 "
        "{%0,%1,%2,%3}, {%4,%5,%6,%7}, {%8,%9}, {%0,%1,%2,%3};"
        : "+f"(c[0]), "+f"(c[1]), "+f"(c[2]), "+f"(c[3])
        : "r"(a[0]), "r"(a[1]), "r"(a[2]), "r"(a[3]), "r"(b[0]), "r"(b[1]));
}
__device__ __forceinline__ void cp16(uint32_t dst, const void* src) {
    asm volatile("cp.async.cg.shared.global [%0], [%1], 16;" :: "r"(dst), "l"(src));
}

// =================================================================================
// fp32 -> fp16 2-level split: x = h + l + O(2^-23 x)   (residual exact in fp32)
// =================================================================================
__global__ __launch_bounds__(256) void split2h_kernel(
    const float* __restrict__ x, unsigned short* __restrict__ h,
    unsigned short* __restrict__ l, int n4)
{
    int i = blockIdx.x * 256 + threadIdx.x;
    if (i >= n4) return;
    float4 v = ((const float4*)x)[i];
    float vv[4] = { v.x, v.y, v.z, v.w };
    unsigned short hh[4], ll[4];
#pragma unroll
    for (int j = 0; j < 4; j++) {
        __half hb = __float2half_rn(vv[j]);
        float r1 = vv[j] - __half2float(hb);
        __half lb = __float2half_rn(r1);
        hh[j] = __half_as_ushort(hb);
        ll[j] = __half_as_ushort(lb);
    }
    ((ushort4*)h)[i] = make_ushort4(hh[0], hh[1], hh[2], hh[3]);
    ((ushort4*)l)[i] = make_ushort4(ll[0], ll[1], ll[2], ll[3]);
}

// =================================================================================
// 2-level fp16 mma GEMM:  C[M,1024] = sum_passes A_la @ B_lb^T + bias
// CTA tile 128(M) x 64(N), 256 thr: 8 warps as 4(m) x 2(n), warp tile m32 x n32.
// KC=32, cp.async 2-stage, ldmatrix. 2 CTAs/SM.
// NPASS=4 (hh,hl,lh,ll: 2^-23) for Q/K;  NPASS=3 (2^-22) for V/FC.
// =================================================================================
#define KC         32
#define NCHUNK     (D_MODEL / KC)       // 32
#define TLD        80                    // bytes per smem row (40 halfs)
#define AT_BYTES   (128 * TLD)           // 10240
#define BT_BYTES   (64 * TLD)            // 5120
#define STAGE      (2 * AT_BYTES + 2 * BT_BYTES)   // 30720
#define GSMEM2     (2 * STAGE)           // 61440

template<int NPASS>
__global__ void __launch_bounds__(256, 2) gemm_2h(
    const unsigned short* __restrict__ A0, const unsigned short* __restrict__ A1,
    const unsigned short* __restrict__ B0, const unsigned short* __restrict__ B1,
    const float* __restrict__ bias, float* __restrict__ C)
{
    extern __shared__ char smc[];
    const uint32_t sbase = smem_u32(smc);
    const int tid = threadIdx.x, wid = tid >> 5, lane = tid & 31;
    const int bn = blockIdx.x, bm = blockIdx.y;
    const int wm = wid & 3, wn = wid >> 2;

    const unsigned short* srcs[4];
    srcs[0] = A0 + (size_t)bm * 128 * D_MODEL;
    srcs[1] = A1 + (size_t)bm * 128 * D_MODEL;
    srcs[2] = B0 + (size_t)bn * 64 * D_MODEL;
    srcs[3] = B1 + (size_t)bn * 64 * D_MODEL;

    float acc[2][4][4];
#pragma unroll
    for (int i = 0; i < 2; i++)
#pragma unroll
        for (int j = 0; j < 4; j++)
#pragma unroll
            for (int v = 0; v < 4; v++) acc[i][j][v] = 0.f;

    const uint32_t a_l = (uint32_t)(wm * 32 + (lane & 15)) * TLD + ((lane >> 4) & 1) * 16;
    const uint32_t b_l = (uint32_t)(wn * 32 + (lane & 7) + ((lane >> 4) & 1) * 8) * TLD
                       + ((lane >> 3) & 1) * 16;

    auto fill = [&](int c, int s) {
        const uint32_t base = sbase + (uint32_t)s * STAGE;
#pragma unroll
        for (int n = 0; n < 6; n++) {
            int i = tid + n * 256;                  // 0..1535
            bool isA = i < 1024;
            int j   = isA ? i : i - 1024;
            int lev = isA ? (j >> 9) : (j >> 8);
            int r   = isA ? ((j >> 2) & 127) : ((j >> 2) & 63);
            int c16 = j & 3;
            const unsigned short* src = srcs[(isA ? 0 : 2) + lev]
                + (size_t)r * D_MODEL + c * KC + c16 * 8;
            uint32_t dst = base + (isA ? (uint32_t)lev * AT_BYTES
                                       : 2u * AT_BYTES + (uint32_t)lev * BT_BYTES)
                         + (uint32_t)r * TLD + c16 * 16;
            cp16(dst, src);
        }
        asm volatile("cp.async.commit_group;" ::: "memory");
    };

    fill(0, 0);
    fill(1, 1);

    constexpr int PA[4] = { 0, 0, 1, 1 };
    constexpr int PB[4] = { 0, 1, 0, 1 };

    for (int c = 0; c < NCHUNK; c++) {
        if (c + 1 < NCHUNK)
            asm volatile("cp.async.wait_group 1;" ::: "memory");
        else
            asm volatile("cp.async.wait_group 0;" ::: "memory");
        __syncthreads();

        const int s = c & 1;
        const uint32_t abase = sbase + (uint32_t)s * STAGE;
        const uint32_t bbase = abase + 2 * AT_BYTES;

#pragma unroll
        for (int kb = 0; kb < 2; kb++) {
            const uint32_t kbyte = kb * 32;
            uint32_t af[2][2][4], bfr[2][2][4];
#pragma unroll
            for (int lv = 0; lv < 2; lv++) {
#pragma unroll
                for (int mt = 0; mt < 2; mt++)
                    ldsm_x4(af[lv][mt], abase + lv * AT_BYTES + a_l + mt * (16 * TLD) + kbyte);
#pragma unroll
                for (int np = 0; np < 2; np++)
                    ldsm_x4(bfr[lv][np], bbase + lv * BT_BYTES + b_l + np * (16 * TLD) + kbyte);
            }
#pragma unroll
            for (int p = 0; p < NPASS; p++) {
#pragma unroll
                for (int mt = 0; mt < 2; mt++)
#pragma unroll
                    for (int nt = 0; nt < 4; nt++)
                        mma_f16(acc[mt][nt], af[PA[p]][mt],
                                &bfr[PB[p]][nt >> 1][(nt & 1) * 2]);
            }
        }
        __syncthreads();
        if (c + 2 < NCHUNK) fill(c + 2, s);
    }

    // epilogue: + bias, fp32 store
    const int qr = lane >> 2;
#pragma unroll
    for (int mt = 0; mt < 2; mt++) {
        int row0 = bm * 128 + wm * 32 + mt * 16 + qr;
#pragma unroll
        for (int nt = 0; nt < 4; nt++) {
            int col = bn * 64 + wn * 32 + nt * 8 + (lane & 3) * 2;
            float2 v0, v1;
            v0.x = acc[mt][nt][0] + bias[col];
            v0.y = acc[mt][nt][1] + bias[col + 1];
            v1.x = acc[mt][nt][2] + bias[col];
            v1.y = acc[mt][nt][3] + bias[col + 1];
            *(float2*)(C + (size_t)row0 * D_MODEL + col)       = v0;
            *(float2*)(C + (size_t)(row0 + 8) * D_MODEL + col) = v1;
        }
    }
}

// =================================================================================
// Fused attention block (fp32, from round 1)
// =================================================================================
#define BQ     32
#define KT     128
#define QS_LD  68
#define KS_LD  69
#define PS_LD  1032
#define ATTN_SMEM_BYTES ((BQ * QS_LD + KT * KS_LD + BQ * PS_LD) * 4)

__global__ __launch_bounds__(256) void attn_kernel(
    const unsigned char* __restrict__ mask,
    float* __restrict__ attn_out)
{
    extern __shared__ float smf[];
    float* Qs = smf;
    float* Ks = Qs + BQ * QS_LD;
    float* Ps = Ks + KT * KS_LD;

    const int t  = threadIdx.x;
    const int qt = blockIdx.x;
    const int h  = blockIdx.y;
    const int b  = blockIdx.z;
    const int q0 = qt * BQ;

#pragma unroll
    for (int i = 0; i < 2; i++) {
        int idx = t + i * 256;
        int r  = idx >> 4;
        int d4 = (idx & 15) << 2;
        float4 v = *(const float4*)&g_qh[((size_t)(b * SEQ + q0 + r)) * D_MODEL + h * DKH + d4];
        *(float4*)&Qs[r * QS_LD + d4] = v;
    }
    __syncthreads();

    const int rg = (t >> 5) << 2;
    const int cg = t & 31;

    for (int kt = 0; kt < SEQ / KT; kt++) {
        if (kt) __syncthreads();
#pragma unroll
        for (int i = 0; i < 8; i++) {
            int idx = t + i * 256;
            int n  = idx >> 4;
            int d4 = (idx & 15) << 2;
            float4 v = *(const float4*)&g_kh[((size_t)(b * SEQ + kt * KT + n)) * D_MODEL + h * DKH + d4];
            Ks[n * KS_LD + d4 + 0] = v.x;
            Ks[n * KS_LD + d4 + 1] = v.y;
            Ks[n * KS_LD + d4 + 2] = v.z;
            Ks[n * KS_LD + d4 + 3] = v.w;
        }
        __syncthreads();

        float a[4][4];
#pragma unroll
        for (int i = 0; i < 4; i++)
#pragma unroll
            for (int j = 0; j < 4; j++) a[i][j] = 0.f;

#pragma unroll 8
        for (int d = 0; d < DKH; d++) {
            float qv[4], kv[4];
#pragma unroll
            for (int i = 0; i < 4; i++) qv[i] = Qs[(rg + i) * QS_LD + d];
#pragma unroll
            for (int j = 0; j < 4; j++) kv[j] = Ks[(cg + 32 * j) * KS_LD + d];
#pragma unroll
            for (int i = 0; i < 4; i++)
#pragma unroll
                for (int j = 0; j < 4; j++) a[i][j] += qv[i] * kv[j];
        }

        const unsigned char* mbase = mask + ((size_t)b * SEQ + q0) * SEQ + (size_t)kt * KT;
#pragma unroll
        for (int i = 0; i < 4; i++) {
#pragma unroll
            for (int j = 0; j < 4; j++) {
                int cc = cg + 32 * j;
                float v = a[i][j] * 0.125f;
                if (mbase[(size_t)(rg + i) * SEQ + cc]) v = -1e9f;
                Ps[(rg + i) * PS_LD + kt * KT + cc] = v;
            }
        }
    }
    __syncthreads();

    {
        int row = t >> 3, sub = t & 7;
        float* pr = Ps + row * PS_LD;
        float m = -1e30f;
        for (int cc = sub; cc < SEQ; cc += 8) m = fmaxf(m, pr[cc]);
#pragma unroll
        for (int o = 4; o > 0; o >>= 1) m = fmaxf(m, __shfl_xor_sync(0xffffffffu, m, o, 8));
        float s = 0.f;
        for (int cc = sub; cc < SEQ; cc += 8) { float e = __expf(pr[cc] - m); pr[cc] = e; s += e; }
#pragma unroll
        for (int o = 4; o > 0; o >>= 1) s += __shfl_xor_sync(0xffffffffu, s, o, 8);
        float inv = 1.0f / s;
        for (int cc = sub; cc < SEQ; cc += 8) pr[cc] *= inv;
    }
    __syncthreads();

    if (attn_out) {
        float* ab = attn_out + (((size_t)(b * NHEAD + h)) * SEQ + q0) * SEQ;
#pragma unroll
        for (int i = 0; i < 32; i++) {
            int idx = t + i * 256;
            int r  = idx >> 8;
            int c4 = (idx & 255) << 2;
            *(float4*)&ab[(size_t)r * SEQ + c4] = *(const float4*)&Ps[r * PS_LD + c4];
        }
    }

    float o[4][2];
#pragma unroll
    for (int i = 0; i < 4; i++) { o[i][0] = 0.f; o[i][1] = 0.f; }
    const int c0 = t & 31;

    for (int kt = 0; kt < SEQ / KT; kt++) {
        __syncthreads();
#pragma unroll
        for (int i = 0; i < 8; i++) {
            int idx = t + i * 256;
            int n  = idx >> 4;
            int d4 = (idx & 15) << 2;
            float4 v = *(const float4*)&g_vh[((size_t)(b * SEQ + kt * KT + n)) * D_MODEL + h * DKH + d4];
            Ks[n * KS_LD + d4 + 0] = v.x;
            Ks[n * KS_LD + d4 + 1] = v.y;
            Ks[n * KS_LD + d4 + 2] = v.z;
            Ks[n * KS_LD + d4 + 3] = v.w;
        }
        __syncthreads();

#pragma unroll 8
        for (int n = 0; n < KT; n++) {
            float v0 = Ks[n * KS_LD + c0];
            float v1 = Ks[n * KS_LD + c0 + 32];
#pragma unroll
            for (int i = 0; i < 4; i++) {
                float p = Ps[(rg + i) * PS_LD + kt * KT + n];
                o[i][0] += p * v0;
                o[i][1] += p * v1;
            }
        }
    }

#pragma unroll
    for (int i = 0; i < 4; i++) {
        float* dst = &g_ctx[((size_t)(b * SEQ + q0 + rg + i)) * D_MODEL + h * DKH];
        dst[c0]      = o[i][0];
        dst[c0 + 32] = o[i][1];
    }
}

// =================================================================================
// Residual add + LayerNorm
// =================================================================================
__global__ __launch_bounds__(256) void ln_kernel(
    const float* __restrict__ fc, const float* __restrict__ resid,
    const float* __restrict__ gamma, const float* __restrict__ beta,
    float* __restrict__ out)
{
    __shared__ float xs[D_MODEL];
    __shared__ float rs[8], rss[8];

    const int row = blockIdx.x;
    const int t   = threadIdx.x;
    const float* f = fc    + (size_t)row * D_MODEL;
    const float* r = resid + (size_t)row * D_MODEL;

    float s = 0.f, ss = 0.f;
    for (int i = t; i < D_MODEL; i += 256) {
        float x = f[i] + r[i];
        xs[i] = x;
        s += x; ss += x * x;
    }
#pragma unroll
    for (int o = 16; o > 0; o >>= 1) {
        s  += __shfl_xor_sync(0xffffffffu, s, o);
        ss += __shfl_xor_sync(0xffffffffu, ss, o);
    }
    int w = t >> 5, lane = t & 31;
    if (lane == 0) { rs[w] = s; rss[w] = ss; }
    __syncthreads();
    float ts = 0.f, tss = 0.f;
#pragma unroll
    for (int i = 0; i < 8; i++) { ts += rs[i]; tss += rss[i]; }
    float mu  = ts * (1.0f / D_MODEL);
    float var = tss * (1.0f / D_MODEL) - mu * mu;
    float kk  = rsqrtf(var + 1e-5f);

    for (int i = t; i < D_MODEL; i += 256)
        out[(size_t)row * D_MODEL + i] = (xs[i] - mu) * kk * gamma[i] + beta[i];
}

// =================================================================================
// launch
// =================================================================================
extern "C" void kernel_launch(void* const* d_in, const int* in_sizes, int n_in,
                              void* d_out, int out_size)
{
    const float* q    = (const float*)d_in[0];
    const float* k    = (const float*)d_in[1];
    const float* v    = (const float*)d_in[2];
    const unsigned char* mask = (const unsigned char*)d_in[3];
    const float* w_q  = (const float*)d_in[4];
    const float* b_q  = (const float*)d_in[5];
    const float* w_k  = (const float*)d_in[6];
    const float* b_k  = (const float*)d_in[7];
    const float* w_v  = (const float*)d_in[8];
    const float* b_v  = (const float*)d_in[9];
    const float* w_fc = (const float*)d_in[10];
    const float* b_fc = (const float*)d_in[11];
    const float* ln_g = (const float*)d_in[12];
    const float* ln_b = (const float*)d_in[13];
    float* out = (float*)d_out;

    float *qh, *kh, *vh, *ctx, *fc;
    unsigned short *a0, *a1, *b0, *b1;
    cudaGetSymbolAddress((void**)&qh,  g_qh);
    cudaGetSymbolAddress((void**)&kh,  g_kh);
    cudaGetSymbolAddress((void**)&vh,  g_vh);
    cudaGetSymbolAddress((void**)&ctx, g_ctx);
    cudaGetSymbolAddress((void**)&fc,  g_fc);
    cudaGetSymbolAddress((void**)&a0,  g_a0);
    cudaGetSymbolAddress((void**)&a1,  g_a1);
    cudaGetSymbolAddress((void**)&b0,  g_b0);
    cudaGetSymbolAddress((void**)&b1,  g_b1);

    const long long xe = (long long)MROWS * D_MODEL;
    const long long ae = (long long)BATCH * NHEAD * SEQ * SEQ;
    float* attn_out = nullptr;
    float* x_out    = out;
    if ((long long)out_size >= xe + ae) {
        attn_out = out + xe;
    } else if ((long long)out_size == ae) {
        attn_out = out;
        x_out = nullptr;
    }

    cudaFuncSetAttribute(gemm_2h<4>, cudaFuncAttributeMaxDynamicSharedMemorySize, GSMEM2);
    cudaFuncSetAttribute(gemm_2h<3>, cudaFuncAttributeMaxDynamicSharedMemorySize, GSMEM2);
    cudaFuncSetAttribute(attn_kernel, cudaFuncAttributeMaxDynamicSharedMemorySize,
                         ATTN_SMEM_BYTES);

    const int nA4 = MROWS * D_MODEL / 4;
    const int nW4 = D_MODEL * D_MODEL / 4;
    dim3 gb(256);
    dim3 gg(D_MODEL / 64, MROWS / 128);    // (16, 64)

    // Q projection (4-pass: 2^-23)
    split2h_kernel<<<nA4 / 256, gb>>>(q, a0, a1, nA4);
    split2h_kernel<<<nW4 / 256, gb>>>(w_q, b0, b1, nW4);
    gemm_2h<4><<<gg, gb, GSMEM2>>>(a0, a1, b0, b1, b_q, qh);
    // K projection (4-pass)
    split2h_kernel<<<nA4 / 256, gb>>>(k, a0, a1, nA4);
    split2h_kernel<<<nW4 / 256, gb>>>(w_k, b0, b1, nW4);
    gemm_2h<4><<<gg, gb, GSMEM2>>>(a0, a1, b0, b1, b_k, kh);
    // V projection (3-pass)
    split2h_kernel<<<nA4 / 256, gb>>>(v, a0, a1, nA4);
    split2h_kernel<<<nW4 / 256, gb>>>(w_v, b0, b1, nW4);
    gemm_2h<3><<<gg, gb, GSMEM2>>>(a0, a1, b0, b1, b_v, vh);

    // attention
    dim3 ag(SEQ / BQ, NHEAD, BATCH);
    attn_kernel<<<ag, gb, ATTN_SMEM_BYTES>>>(mask, attn_out);

    // FC (3-pass)
    split2h_kernel<<<nA4 / 256, gb>>>(ctx, a0, a1, nA4);
    split2h_kernel<<<nW4 / 256, gb>>>(w_fc, b0, b1, nW4);
    gemm_2h<3><<<gg, gb, GSMEM2>>>(a0, a1, b0, b1, b_fc, fc);

    if (x_out)
        ln_kernel<<<MROWS, gb>>>(fc, q, ln_g, ln_b, x_out);
}

// round 7
// speedup vs baseline: 2.1973x; 1.5308x over previous
#include <cuda_runtime.h>
#include <cuda_fp16.h>
#include <cstdint>
#include <cstddef>

#define D_MODEL 1024
#define NHEAD   16
#define DKH     64
#define BATCH   8
#define SEQ     1024
#define MROWS   (BATCH * SEQ)   // 8192

// ---------------- scratch (device globals: no cudaMalloc allowed) ----------------
__device__ float g_qh[MROWS * D_MODEL];
__device__ float g_kh[MROWS * D_MODEL];
__device__ float g_vh[MROWS * D_MODEL];
__device__ float g_ctx[MROWS * D_MODEL];
__device__ float g_fc[MROWS * D_MODEL];
// fp16 2-level split operands (GEMM activations; also reused for Q-split in attention)
__device__ __align__(16) unsigned short g_a0[MROWS * D_MODEL];
__device__ __align__(16) unsigned short g_a1[MROWS * D_MODEL];
__device__ __align__(16) unsigned short g_b0[D_MODEL * D_MODEL];
__device__ __align__(16) unsigned short g_b1[D_MODEL * D_MODEL];
// attention-only splits
__device__ __align__(16) unsigned short g_k0s[MROWS * D_MODEL];
__device__ __align__(16) unsigned short g_k1s[MROWS * D_MODEL];
__device__ __align__(16) unsigned short g_v0t[MROWS * D_MODEL];   // [bh][d][token]
__device__ __align__(16) unsigned short g_v1t[MROWS * D_MODEL];

// =================================================================================
// helpers
// =================================================================================
__device__ __forceinline__ uint32_t smem_u32(const void* p) {
    uint32_t a;
    asm("{ .reg .u64 t; cvta.to.shared.u64 t, %1; cvt.u32.u64 %0, t; }" : "=r"(a) : "l"(p));
    return a;
}
__device__ __forceinline__ void ldsm_x4(uint32_t* r, uint32_t addr) {
    asm volatile("ldmatrix.sync.aligned.m8n8.x4.shared.b16 {%0,%1,%2,%3}, [%4];"
        : "=r"(r[0]), "=r"(r[1]), "=r"(r[2]), "=r"(r[3]) : "r"(addr));
}
__device__ __forceinline__ void mma_f16(float* c, const uint32_t* a, const uint32_t* b) {
    asm volatile("mma.sync.aligned.m16n8k16.row.col.f32.f16.f16.f32 "
        "{%0,%1,%2,%3}, {%4,%5,%6,%7}, {%8,%9}, {%0,%1,%2,%3};"
        : "+f"(c[0]), "+f"(c[1]), "+f"(c[2]), "+f"(c[3])
        : "r"(a[0]), "r"(a[1]), "r"(a[2]), "r"(a[3]), "r"(b[0]), "r"(b[1]));
}
__device__ __forceinline__ void cp16(uint32_t dst, const void* src) {
    asm volatile("cp.async.cg.shared.global [%0], [%1], 16;" :: "r"(dst), "l"(src));
}

// =================================================================================
// fp32 -> fp16 2-level split
// =================================================================================
__global__ __launch_bounds__(256) void split2h_kernel(
    const float* __restrict__ x, unsigned short* __restrict__ h,
    unsigned short* __restrict__ l, int n4)
{
    int i = blockIdx.x * 256 + threadIdx.x;
    if (i >= n4) return;
    float4 v = ((const float4*)x)[i];
    float vv[4] = { v.x, v.y, v.z, v.w };
    unsigned short hh[4], ll[4];
#pragma unroll
    for (int j = 0; j < 4; j++) {
        __half hb = __float2half_rn(vv[j]);
        float r1 = vv[j] - __half2float(hb);
        __half lb = __float2half_rn(r1);
        hh[j] = __half_as_ushort(hb);
        ll[j] = __half_as_ushort(lb);
    }
    ((ushort4*)h)[i] = make_ushort4(hh[0], hh[1], hh[2], hh[3]);
    ((ushort4*)l)[i] = make_ushort4(ll[0], ll[1], ll[2], ll[3]);
}

// =================================================================================
// V transpose + split:  g_vh[token][h*64+d] -> g_v{0,1}t[(bh*64+d)*1024 + token]
// =================================================================================
__global__ __launch_bounds__(256) void vtrans_kernel()
{
    __shared__ float ttile[32][33];
    const int bh = blockIdx.z, b = bh >> 4, h = bh & 15;
    const int t0 = blockIdx.x * 32, d0 = blockIdx.y * 32;
    const int tx = threadIdx.x, ty = threadIdx.y;
#pragma unroll
    for (int j = 0; j < 4; j++) {
        int tok = t0 + ty + j * 8;
        ttile[ty + j * 8][tx] =
            g_vh[(size_t)(b * SEQ + tok) * D_MODEL + h * DKH + d0 + tx];
    }
    __syncthreads();
#pragma unroll
    for (int j = 0; j < 4; j++) {
        int d = d0 + ty + j * 8;
        float x = ttile[tx][ty + j * 8];
        __half hb = __float2half_rn(x);
        __half lb = __float2half_rn(x - __half2float(hb));
        size_t o = ((size_t)bh * DKH + d) * SEQ + t0 + tx;
        g_v0t[o] = __half_as_ushort(hb);
        g_v1t[o] = __half_as_ushort(lb);
    }
}

// =================================================================================
// 2-level fp16 mma GEMM (unchanged)
// =================================================================================
#define KC         32
#define NCHUNK     (D_MODEL / KC)
#define TLD        80
#define AT_BYTES   (128 * TLD)
#define BT_BYTES   (64 * TLD)
#define STAGE      (2 * AT_BYTES + 2 * BT_BYTES)
#define GSMEM2     (2 * STAGE)

template<int NPASS>
__global__ void __launch_bounds__(256, 2) gemm_2h(
    const unsigned short* __restrict__ A0, const unsigned short* __restrict__ A1,
    const unsigned short* __restrict__ B0, const unsigned short* __restrict__ B1,
    const float* __restrict__ bias, float* __restrict__ C)
{
    extern __shared__ char smc[];
    const uint32_t sbase = smem_u32(smc);
    const int tid = threadIdx.x, wid = tid >> 5, lane = tid & 31;
    const int bn = blockIdx.x, bm = blockIdx.y;
    const int wm = wid & 3, wn = wid >> 2;

    const unsigned short* srcs[4];
    srcs[0] = A0 + (size_t)bm * 128 * D_MODEL;
    srcs[1] = A1 + (size_t)bm * 128 * D_MODEL;
    srcs[2] = B0 + (size_t)bn * 64 * D_MODEL;
    srcs[3] = B1 + (size_t)bn * 64 * D_MODEL;

    float acc[2][4][4];
#pragma unroll
    for (int i = 0; i < 2; i++)
#pragma unroll
        for (int j = 0; j < 4; j++)
#pragma unroll
            for (int v = 0; v < 4; v++) acc[i][j][v] = 0.f;

    const uint32_t a_l = (uint32_t)(wm * 32 + (lane & 15)) * TLD + ((lane >> 4) & 1) * 16;
    const uint32_t b_l = (uint32_t)(wn * 32 + (lane & 7) + ((lane >> 4) & 1) * 8) * TLD
                       + ((lane >> 3) & 1) * 16;

    auto fill = [&](int c, int s) {
        const uint32_t base = sbase + (uint32_t)s * STAGE;
#pragma unroll
        for (int n = 0; n < 6; n++) {
            int i = tid + n * 256;
            bool isA = i < 1024;
            int j   = isA ? i : i - 1024;
            int lev = isA ? (j >> 9) : (j >> 8);
            int r   = isA ? ((j >> 2) & 127) : ((j >> 2) & 63);
            int c16 = j & 3;
            const unsigned short* src = srcs[(isA ? 0 : 2) + lev]
                + (size_t)r * D_MODEL + c * KC + c16 * 8;
            uint32_t dst = base + (isA ? (uint32_t)lev * AT_BYTES
                                       : 2u * AT_BYTES + (uint32_t)lev * BT_BYTES)
                         + (uint32_t)r * TLD + c16 * 16;
            cp16(dst, src);
        }
        asm volatile("cp.async.commit_group;" ::: "memory");
    };

    fill(0, 0);
    fill(1, 1);

    constexpr int PA[4] = { 0, 0, 1, 1 };
    constexpr int PB[4] = { 0, 1, 0, 1 };

    for (int c = 0; c < NCHUNK; c++) {
        if (c + 1 < NCHUNK)
            asm volatile("cp.async.wait_group 1;" ::: "memory");
        else
            asm volatile("cp.async.wait_group 0;" ::: "memory");
        __syncthreads();

        const int s = c & 1;
        const uint32_t abase = sbase + (uint32_t)s * STAGE;
        const uint32_t bbase = abase + 2 * AT_BYTES;

#pragma unroll
        for (int kb = 0; kb < 2; kb++) {
            const uint32_t kbyte = kb * 32;
            uint32_t af[2][2][4], bfr[2][2][4];
#pragma unroll
            for (int lv = 0; lv < 2; lv++) {
#pragma unroll
                for (int mt = 0; mt < 2; mt++)
                    ldsm_x4(af[lv][mt], abase + lv * AT_BYTES + a_l + mt * (16 * TLD) + kbyte);
#pragma unroll
                for (int np = 0; np < 2; np++)
                    ldsm_x4(bfr[lv][np], bbase + lv * BT_BYTES + b_l + np * (16 * TLD) + kbyte);
            }
#pragma unroll
            for (int p = 0; p < NPASS; p++) {
#pragma unroll
                for (int mt = 0; mt < 2; mt++)
#pragma unroll
                    for (int nt = 0; nt < 4; nt++)
                        mma_f16(acc[mt][nt], af[PA[p]][mt],
                                &bfr[PB[p]][nt >> 1][(nt & 1) * 2]);
            }
        }
        __syncthreads();
        if (c + 2 < NCHUNK) fill(c + 2, s);
    }

    const int qr = lane >> 2;
#pragma unroll
    for (int mt = 0; mt < 2; mt++) {
        int row0 = bm * 128 + wm * 32 + mt * 16 + qr;
#pragma unroll
        for (int nt = 0; nt < 4; nt++) {
            int col = bn * 64 + wn * 32 + nt * 8 + (lane & 3) * 2;
            float2 v0, v1;
            v0.x = acc[mt][nt][0] + bias[col];
            v0.y = acc[mt][nt][1] + bias[col + 1];
            v1.x = acc[mt][nt][2] + bias[col];
            v1.y = acc[mt][nt][3] + bias[col + 1];
            *(float2*)(C + (size_t)row0 * D_MODEL + col)       = v0;
            *(float2*)(C + (size_t)(row0 + 8) * D_MODEL + col) = v1;
        }
    }
}

// =================================================================================
// mma attention: CTA = (b, h, 32 q-rows), 256 thr.
// =================================================================================
#define PS_LD     1032
#define PS_BYTES  (32 * PS_LD * 4)       // 132096
#define KROWB     144
#define KLEV      (128 * KROWB)          // 18432
#define KSTG      (2 * KLEV)             // 36864
#define VROWB     272
#define VLEV      (64 * VROWB)           // 17408
#define VSTG      (2 * VLEV)             // 34816
#define ATTN_SMEM (PS_BYTES + 2 * KSTG)  // 205824

__global__ __launch_bounds__(256) void attn_mma(
    const unsigned char* __restrict__ mask, float* __restrict__ attn_out)
{
    extern __shared__ char smraw[];
    float* Ps = (float*)smraw;
    const uint32_t tbase = smem_u32(smraw) + PS_BYTES;

    const int t = threadIdx.x, w = t >> 5, lane = t & 31;
    const int qt = blockIdx.x, h = blockIdx.y, b = blockIdx.z;
    const int q0 = qt * 32;

    // ---- Q a-fragments from global (g_a0/g_a1 = fp16 split of g_qh) ----
    uint32_t af[2][2][4][4];
    {
        const unsigned short* qs[2] = { g_a0, g_a1 };
        const int r0 = lane >> 2;
        const int c0 = (lane & 3) * 2;
#pragma unroll
        for (int lv = 0; lv < 2; lv++)
#pragma unroll
            for (int mt = 0; mt < 2; mt++)
#pragma unroll
                for (int ks = 0; ks < 4; ks++) {
                    size_t base = (size_t)(b * SEQ + q0 + mt * 16 + r0) * D_MODEL
                                + h * DKH + ks * 16 + c0;
                    af[lv][mt][ks][0] = *(const uint32_t*)(qs[lv] + base);
                    af[lv][mt][ks][1] = *(const uint32_t*)(qs[lv] + base + 8 * D_MODEL);
                    af[lv][mt][ks][2] = *(const uint32_t*)(qs[lv] + base + 8);
                    af[lv][mt][ks][3] = *(const uint32_t*)(qs[lv] + base + 8 * D_MODEL + 8);
                }
    }

    // ---- score phase: 8 K-tiles of 128 tokens, double-buffered ----
    auto kfill = [&](int kt, int s) {
#pragma unroll
        for (int n = 0; n < 8; n++) {
            int i = t + n * 256;                 // 0..2047
            int lv = i >> 10, j = i & 1023;
            int r = j >> 3, u = j & 7;           // K row = 64 halfs = 128B
            const unsigned short* src = (lv ? g_k1s : g_k0s)
                + (size_t)(b * SEQ + kt * 128 + r) * D_MODEL + h * DKH + u * 8;
            cp16(tbase + s * KSTG + lv * KLEV + (uint32_t)r * KROWB + u * 16, src);
        }
        asm volatile("cp.async.commit_group;" ::: "memory");
    };
    const uint32_t krow = (uint32_t)(w * 16 + (lane & 7) + ((lane >> 4) & 1) * 8) * KROWB
                        + ((lane >> 3) & 1) * 16;
    kfill(0, 0);
    kfill(1, 1);

    for (int kt = 0; kt < 8; kt++) {
        if (kt < 7) asm volatile("cp.async.wait_group 1;" ::: "memory");
        else        asm volatile("cp.async.wait_group 0;" ::: "memory");
        __syncthreads();
        const uint32_t kb = tbase + (kt & 1) * KSTG;

        uint32_t bf[2][4][4];
#pragma unroll
        for (int lv = 0; lv < 2; lv++)
#pragma unroll
            for (int ks = 0; ks < 4; ks++)
                ldsm_x4(bf[lv][ks], kb + lv * KLEV + krow + ks * 32);

        float acc[2][2][4];
#pragma unroll
        for (int i = 0; i < 2; i++)
#pragma unroll
            for (int j = 0; j < 2; j++)
#pragma unroll
                for (int v = 0; v < 4; v++) acc[i][j][v] = 0.f;

#pragma unroll
        for (int ks = 0; ks < 4; ks++) {
#pragma unroll
            for (int mt = 0; mt < 2; mt++)
#pragma unroll
                for (int nt = 0; nt < 2; nt++) {
                    mma_f16(acc[mt][nt], af[0][mt][ks], &bf[0][ks][nt * 2]);
                    mma_f16(acc[mt][nt], af[0][mt][ks], &bf[1][ks][nt * 2]);
                    mma_f16(acc[mt][nt], af[1][mt][ks], &bf[0][ks][nt * 2]);
                }
        }

        // scale + mask + store
#pragma unroll
        for (int mt = 0; mt < 2; mt++) {
#pragma unroll
            for (int nt = 0; nt < 2; nt++) {
                int row = mt * 16 + (lane >> 2);
                int col = kt * 128 + w * 16 + nt * 8 + (lane & 3) * 2;
                const unsigned char* mp0 =
                    mask + (size_t)(b * SEQ + q0 + row) * SEQ + col;
                const unsigned char* mp1 = mp0 + 8 * SEQ;
                float2 v0, v1;
                v0.x = mp0[0] ? -1e9f : acc[mt][nt][0] * 0.125f;
                v0.y = mp0[1] ? -1e9f : acc[mt][nt][1] * 0.125f;
                v1.x = mp1[0] ? -1e9f : acc[mt][nt][2] * 0.125f;
                v1.y = mp1[1] ? -1e9f : acc[mt][nt][3] * 0.125f;
                *(float2*)&Ps[row * PS_LD + col]       = v0;
                *(float2*)&Ps[(row + 8) * PS_LD + col] = v1;
            }
        }
        __syncthreads();
        if (kt + 2 < 8) kfill(kt + 2, kt & 1);
    }
    __syncthreads();

    // ---- row softmax (8 threads per row) ----
    {
        int row = t >> 3, sub = t & 7;
        float* pr = Ps + row * PS_LD;
        float m = -1e30f;
        for (int cc = sub; cc < SEQ; cc += 8) m = fmaxf(m, pr[cc]);
#pragma unroll
        for (int o = 4; o > 0; o >>= 1) m = fmaxf(m, __shfl_xor_sync(0xffffffffu, m, o, 8));
        float s = 0.f;
        for (int cc = sub; cc < SEQ; cc += 8) { float e = __expf(pr[cc] - m); pr[cc] = e; s += e; }
#pragma unroll
        for (int o = 4; o > 0; o >>= 1) s += __shfl_xor_sync(0xffffffffu, s, o, 8);
        float inv = 1.0f / s;
        for (int cc = sub; cc < SEQ; cc += 8) pr[cc] *= inv;
    }
    __syncthreads();

    // ---- write attn ----
    if (attn_out) {
        float* ab = attn_out + (((size_t)(b * NHEAD + h)) * SEQ + q0) * SEQ;
#pragma unroll
        for (int i = 0; i < 32; i++) {
            int idx = t + i * 256;
            int r  = idx >> 8;
            int c4 = (idx & 255) << 2;
            *(float4*)&ab[(size_t)r * SEQ + c4] = *(const float4*)&Ps[r * PS_LD + c4];
        }
    }
    __syncthreads();

    // ---- PV phase: 8 V-tiles, double-buffered; P fragments built from fp32 smem ----
    // V^T tile row = 128 tokens = 256 BYTES -> 16 cp16 units per row (u = 0..15)
    auto vfill = [&](int kt, int s) {
#pragma unroll
        for (int n = 0; n < 8; n++) {
            int i = t + n * 256;                 // 0..2047
            int lv = i >> 10, j = i & 1023;
            int r = j >> 4, u = j & 15;
            const unsigned short* src = (lv ? g_v1t : g_v0t)
                + ((size_t)(b * NHEAD + h) * DKH + r) * SEQ + kt * 128 + u * 8;
            cp16(tbase + s * VSTG + lv * VLEV + (uint32_t)r * VROWB + u * 16, src);
        }
        asm volatile("cp.async.commit_group;" ::: "memory");
    };
    const int mh = w & 1, nq = w >> 1;
    const uint32_t vrow = (uint32_t)(nq * 16 + (lane & 7) + ((lane >> 4) & 1) * 8) * VROWB
                        + ((lane >> 3) & 1) * 16;
    float oacc[2][4];
#pragma unroll
    for (int i = 0; i < 2; i++)
#pragma unroll
        for (int v = 0; v < 4; v++) oacc[i][v] = 0.f;

    vfill(0, 0);
    vfill(1, 1);

    const int pr0 = mh * 16 + (lane >> 2);
    const int pc0 = (lane & 3) * 2;

    for (int kt = 0; kt < 8; kt++) {
        if (kt < 7) asm volatile("cp.async.wait_group 1;" ::: "memory");
        else        asm volatile("cp.async.wait_group 0;" ::: "memory");
        __syncthreads();
        const uint32_t vb = tbase + (kt & 1) * VSTG;

#pragma unroll
        for (int ks = 0; ks < 8; ks++) {
            uint32_t bv[2][4];
            ldsm_x4(bv[0], vb + vrow + ks * 32);
            ldsm_x4(bv[1], vb + VLEV + vrow + ks * 32);

            int pc = kt * 128 + ks * 16 + pc0;
            float2 p00 = *(float2*)&Ps[pr0 * PS_LD + pc];
            float2 p10 = *(float2*)&Ps[(pr0 + 8) * PS_LD + pc];
            float2 p01 = *(float2*)&Ps[pr0 * PS_LD + pc + 8];
            float2 p11 = *(float2*)&Ps[(pr0 + 8) * PS_LD + pc + 8];

            uint32_t ph[4], pl[4];
            {
                __half2 h0 = __floats2half2_rn(p00.x, p00.y);
                __half2 h1 = __floats2half2_rn(p10.x, p10.y);
                __half2 h2 = __floats2half2_rn(p01.x, p01.y);
                __half2 h3 = __floats2half2_rn(p11.x, p11.y);
                ph[0] = *(uint32_t*)&h0; ph[1] = *(uint32_t*)&h1;
                ph[2] = *(uint32_t*)&h2; ph[3] = *(uint32_t*)&h3;
                float2 f0 = __half22float2(h0), f1 = __half22float2(h1);
                float2 f2 = __half22float2(h2), f3 = __half22float2(h3);
                __half2 l0 = __floats2half2_rn(p00.x - f0.x, p00.y - f0.y);
                __half2 l1 = __floats2half2_rn(p10.x - f1.x, p10.y - f1.y);
                __half2 l2 = __floats2half2_rn(p01.x - f2.x, p01.y - f2.y);
                __half2 l3 = __floats2half2_rn(p11.x - f3.x, p11.y - f3.y);
                pl[0] = *(uint32_t*)&l0; pl[1] = *(uint32_t*)&l1;
                pl[2] = *(uint32_t*)&l2; pl[3] = *(uint32_t*)&l3;
            }
            // passes: Ph*Vh, Ph*Vl, Pl*Vh
            mma_f16(oacc[0], ph, &bv[0][0]);
            mma_f16(oacc[1], ph, &bv[0][2]);
            mma_f16(oacc[0], ph, &bv[1][0]);
            mma_f16(oacc[1], ph, &bv[1][2]);
            mma_f16(oacc[0], pl, &bv[0][0]);
            mma_f16(oacc[1], pl, &bv[0][2]);
        }
        __syncthreads();
        if (kt + 2 < 8) vfill(kt + 2, kt & 1);
    }

    // ---- write O to g_ctx ----
    {
        int orow = b * SEQ + q0 + pr0;
        int ocol = h * DKH + nq * 16 + pc0;
#pragma unroll
        for (int nt = 0; nt < 2; nt++) {
            float2 v0 = { oacc[nt][0], oacc[nt][1] };
            float2 v1 = { oacc[nt][2], oacc[nt][3] };
            *(float2*)&g_ctx[(size_t)orow * D_MODEL + ocol + nt * 8]       = v0;
            *(float2*)&g_ctx[(size_t)(orow + 8) * D_MODEL + ocol + nt * 8] = v1;
        }
    }
}

// =================================================================================
// Residual add + LayerNorm
// =================================================================================
__global__ __launch_bounds__(256) void ln_kernel(
    const float* __restrict__ fc, const float* __restrict__ resid,
    const float* __restrict__ gamma, const float* __restrict__ beta,
    float* __restrict__ out)
{
    __shared__ float xs[D_MODEL];
    __shared__ float rs[8], rss[8];

    const int row = blockIdx.x;
    const int t   = threadIdx.x;
    const float* f = fc    + (size_t)row * D_MODEL;
    const float* r = resid + (size_t)row * D_MODEL;

    float s = 0.f, ss = 0.f;
    for (int i = t; i < D_MODEL; i += 256) {
        float x = f[i] + r[i];
        xs[i] = x;
        s += x; ss += x * x;
    }
#pragma unroll
    for (int o = 16; o > 0; o >>= 1) {
        s  += __shfl_xor_sync(0xffffffffu, s, o);
        ss += __shfl_xor_sync(0xffffffffu, ss, o);
    }
    int w = t >> 5, lane = t & 31;
    if (lane == 0) { rs[w] = s; rss[w] = ss; }
    __syncthreads();
    float ts = 0.f, tss = 0.f;
#pragma unroll
    for (int i = 0; i < 8; i++) { ts += rs[i]; tss += rss[i]; }
    float mu  = ts * (1.0f / D_MODEL);
    float var = tss * (1.0f / D_MODEL) - mu * mu;
    float kk  = rsqrtf(var + 1e-5f);

    for (int i = t; i < D_MODEL; i += 256)
        out[(size_t)row * D_MODEL + i] = (xs[i] - mu) * kk * gamma[i] + beta[i];
}

// =================================================================================
// launch
// =================================================================================
extern "C" void kernel_launch(void* const* d_in, const int* in_sizes, int n_in,
                              void* d_out, int out_size)
{
    const float* q    = (const float*)d_in[0];
    const float* k    = (const float*)d_in[1];
    const float* v    = (const float*)d_in[2];
    const unsigned char* mask = (const unsigned char*)d_in[3];
    const float* w_q  = (const float*)d_in[4];
    const float* b_q  = (const float*)d_in[5];
    const float* w_k  = (const float*)d_in[6];
    const float* b_k  = (const float*)d_in[7];
    const float* w_v  = (const float*)d_in[8];
    const float* b_v  = (const float*)d_in[9];
    const float* w_fc = (const float*)d_in[10];
    const float* b_fc = (const float*)d_in[11];
    const float* ln_g = (const float*)d_in[12];
    const float* ln_b = (const float*)d_in[13];
    float* out = (float*)d_out;

    float *qh, *kh, *vh, *ctx, *fc;
    unsigned short *a0, *a1, *b0, *b1, *k0s, *k1s;
    cudaGetSymbolAddress((void**)&qh,  g_qh);
    cudaGetSymbolAddress((void**)&kh,  g_kh);
    cudaGetSymbolAddress((void**)&vh,  g_vh);
    cudaGetSymbolAddress((void**)&ctx, g_ctx);
    cudaGetSymbolAddress((void**)&fc,  g_fc);
    cudaGetSymbolAddress((void**)&a0,  g_a0);
    cudaGetSymbolAddress((void**)&a1,  g_a1);
    cudaGetSymbolAddress((void**)&b0,  g_b0);
    cudaGetSymbolAddress((void**)&b1,  g_b1);
    cudaGetSymbolAddress((void**)&k0s, g_k0s);
    cudaGetSymbolAddress((void**)&k1s, g_k1s);

    const long long xe = (long long)MROWS * D_MODEL;
    const long long ae = (long long)BATCH * NHEAD * SEQ * SEQ;
    float* attn_out = nullptr;
    float* x_out    = out;
    if ((long long)out_size >= xe + ae) {
        attn_out = out + xe;
    } else if ((long long)out_size == ae) {
        attn_out = out;
        x_out = nullptr;
    }

    cudaFuncSetAttribute(gemm_2h<4>, cudaFuncAttributeMaxDynamicSharedMemorySize, GSMEM2);
    cudaFuncSetAttribute(gemm_2h<3>, cudaFuncAttributeMaxDynamicSharedMemorySize, GSMEM2);
    cudaFuncSetAttribute(attn_mma, cudaFuncAttributeMaxDynamicSharedMemorySize, ATTN_SMEM);

    const int nA4 = MROWS * D_MODEL / 4;
    const int nW4 = D_MODEL * D_MODEL / 4;
    dim3 gb(256);
    dim3 gg(D_MODEL / 64, MROWS / 128);    // (16, 64)

    // projections
    split2h_kernel<<<nA4 / 256, gb>>>(q, a0, a1, nA4);
    split2h_kernel<<<nW4 / 256, gb>>>(w_q, b0, b1, nW4);
    gemm_2h<4><<<gg, gb, GSMEM2>>>(a0, a1, b0, b1, b_q, qh);

    split2h_kernel<<<nA4 / 256, gb>>>(k, a0, a1, nA4);
    split2h_kernel<<<nW4 / 256, gb>>>(w_k, b0, b1, nW4);
    gemm_2h<4><<<gg, gb, GSMEM2>>>(a0, a1, b0, b1, b_k, kh);

    split2h_kernel<<<nA4 / 256, gb>>>(v, a0, a1, nA4);
    split2h_kernel<<<nW4 / 256, gb>>>(w_v, b0, b1, nW4);
    gemm_2h<3><<<gg, gb, GSMEM2>>>(a0, a1, b0, b1, b_v, vh);

    // attention pre-splits: qh -> a0/a1 (activation buffers free now),
    // kh -> k0s/k1s, vh -> v0t/v1t (transposed)
    split2h_kernel<<<nA4 / 256, gb>>>(qh, a0, a1, nA4);
    split2h_kernel<<<nA4 / 256, gb>>>(kh, k0s, k1s, nA4);
    vtrans_kernel<<<dim3(SEQ / 32, DKH / 32, BATCH * NHEAD), dim3(32, 8)>>>();

    dim3 ag(SEQ / 32, NHEAD, BATCH);
    attn_mma<<<ag, gb, ATTN_SMEM>>>(mask, attn_out);

    // FC
    split2h_kernel<<<nA4 / 256, gb>>>(ctx, a0, a1, nA4);
    split2h_kernel<<<nW4 / 256, gb>>>(w_fc, b0, b1, nW4);
    gemm_2h<3><<<gg, gb, GSMEM2>>>(a0, a1, b0, b1, b_fc, fc);

    if (x_out)
        ln_kernel<<<MROWS, gb>>>(fc, q, ln_g, ln_b, x_out);
}

// round 8
// speedup vs baseline: 2.2453x; 1.0218x over previous
#include <cuda_runtime.h>
#include <cuda_fp16.h>
#include <cstdint>
#include <cstddef>

#define D_MODEL 1024
#define NHEAD   16
#define DKH     64
#define BATCH   8
#define SEQ     1024
#define MROWS   (BATCH * SEQ)   // 8192

// ---------------- scratch (device globals: no cudaMalloc allowed) ----------------
__device__ float g_qh[MROWS * D_MODEL];    // carved as Q h/l split (ushort x2)
__device__ float g_vh[MROWS * D_MODEL];    // fp32 V (for vtrans)
__device__ float g_ctx[MROWS * D_MODEL];   // carved as ctx h/l split (ushort x2)
__device__ float g_fc[MROWS * D_MODEL];
// fp16 2-level split operands
__device__ __align__(16) unsigned short g_a0[MROWS * D_MODEL];
__device__ __align__(16) unsigned short g_a1[MROWS * D_MODEL];
__device__ __align__(16) unsigned short g_b0[D_MODEL * D_MODEL];
__device__ __align__(16) unsigned short g_b1[D_MODEL * D_MODEL];
__device__ __align__(16) unsigned short g_k0s[MROWS * D_MODEL];
__device__ __align__(16) unsigned short g_k1s[MROWS * D_MODEL];
__device__ __align__(16) unsigned short g_v0t[MROWS * D_MODEL];   // [bh][d][token]
__device__ __align__(16) unsigned short g_v1t[MROWS * D_MODEL];

// =================================================================================
// helpers
// =================================================================================
__device__ __forceinline__ uint32_t smem_u32(const void* p) {
    uint32_t a;
    asm("{ .reg .u64 t; cvta.to.shared.u64 t, %1; cvt.u32.u64 %0, t; }" : "=r"(a) : "l"(p));
    return a;
}
__device__ __forceinline__ void ldsm_x4(uint32_t* r, uint32_t addr) {
    asm volatile("ldmatrix.sync.aligned.m8n8.x4.shared.b16 {%0,%1,%2,%3}, [%4];"
        : "=r"(r[0]), "=r"(r[1]), "=r"(r[2]), "=r"(r[3]) : "r"(addr));
}
__device__ __forceinline__ void mma_f16(float* c, const uint32_t* a, const uint32_t* b) {
    asm volatile("mma.sync.aligned.m16n8k16.row.col.f32.f16.f16.f32 "
        "{%0,%1,%2,%3}, {%4,%5,%6,%7}, {%8,%9}, {%0,%1,%2,%3};"
        : "+f"(c[0]), "+f"(c[1]), "+f"(c[2]), "+f"(c[3])
        : "r"(a[0]), "r"(a[1]), "r"(a[2]), "r"(a[3]), "r"(b[0]), "r"(b[1]));
}
__device__ __forceinline__ void cp16(uint32_t dst, const void* src) {
    asm volatile("cp.async.cg.shared.global [%0], [%1], 16;" :: "r"(dst), "l"(src));
}
__device__ __forceinline__ ushort2 split_h(float x, float& rem) {
    __half hb = __float2half_rn(x);
    float hf = __half2float(hb);
    __half lb = __float2half_rn(x - hf);
    rem = 0.f;
    return make_ushort2(__half_as_ushort(hb), __half_as_ushort(lb));
}

// =================================================================================
// fp32 -> fp16 2-level split (standalone, for raw inputs / weights)
// =================================================================================
__global__ __launch_bounds__(256) void split2h_kernel(
    const float* __restrict__ x, unsigned short* __restrict__ h,
    unsigned short* __restrict__ l, int n4)
{
    int i = blockIdx.x * 256 + threadIdx.x;
    if (i >= n4) return;
    float4 v = ((const float4*)x)[i];
    float vv[4] = { v.x, v.y, v.z, v.w };
    unsigned short hh[4], ll[4];
#pragma unroll
    for (int j = 0; j < 4; j++) {
        __half hb = __float2half_rn(vv[j]);
        float r1 = vv[j] - __half2float(hb);
        __half lb = __float2half_rn(r1);
        hh[j] = __half_as_ushort(hb);
        ll[j] = __half_as_ushort(lb);
    }
    ((ushort4*)h)[i] = make_ushort4(hh[0], hh[1], hh[2], hh[3]);
    ((ushort4*)l)[i] = make_ushort4(ll[0], ll[1], ll[2], ll[3]);
}

// =================================================================================
// V transpose + split:  g_vh[token][h*64+d] -> g_v{0,1}t[(bh*64+d)*1024 + token]
// =================================================================================
__global__ __launch_bounds__(256) void vtrans_kernel()
{
    __shared__ float ttile[32][33];
    const int bh = blockIdx.z, b = bh >> 4, h = bh & 15;
    const int t0 = blockIdx.x * 32, d0 = blockIdx.y * 32;
    const int tx = threadIdx.x, ty = threadIdx.y;
#pragma unroll
    for (int j = 0; j < 4; j++) {
        int tok = t0 + ty + j * 8;
        ttile[ty + j * 8][tx] =
            g_vh[(size_t)(b * SEQ + tok) * D_MODEL + h * DKH + d0 + tx];
    }
    __syncthreads();
#pragma unroll
    for (int j = 0; j < 4; j++) {
        int d = d0 + ty + j * 8;
        float x = ttile[tx][ty + j * 8];
        __half hb = __float2half_rn(x);
        __half lb = __float2half_rn(x - __half2float(hb));
        size_t o = ((size_t)bh * DKH + d) * SEQ + t0 + tx;
        g_v0t[o] = __half_as_ushort(hb);
        g_v1t[o] = __half_as_ushort(lb);
    }
}

// =================================================================================
// 2-level fp16 mma GEMM, 3-stage cp.async ring, ONE sync per chunk.
// CTA tile 128x64, 8 warps (4m x 2n), warp tile 32x32, KC=32, 2 CTAs/SM.
// SPLIT_OUT: epilogue emits fp16 h/l split directly (no fp32 C).
// =================================================================================
#define KC         32
#define NCHUNK     (D_MODEL / KC)
#define TLD        80
#define AT_BYTES   (128 * TLD)
#define BT_BYTES   (64 * TLD)
#define STAGE      (2 * AT_BYTES + 2 * BT_BYTES)   // 30720
#define GSMEM3     (3 * STAGE)                     // 92160

template<int NPASS, bool SPLIT_OUT>
__global__ void __launch_bounds__(256, 2) gemm_2h(
    const unsigned short* __restrict__ A0, const unsigned short* __restrict__ A1,
    const unsigned short* __restrict__ B0, const unsigned short* __restrict__ B1,
    const float* __restrict__ bias,
    float* __restrict__ C,
    unsigned short* __restrict__ H, unsigned short* __restrict__ L)
{
    extern __shared__ char smc[];
    const uint32_t sbase = smem_u32(smc);
    const int tid = threadIdx.x, wid = tid >> 5, lane = tid & 31;
    const int bn = blockIdx.x, bm = blockIdx.y;
    const int wm = wid & 3, wn = wid >> 2;

    const unsigned short* srcs[4];
    srcs[0] = A0 + (size_t)bm * 128 * D_MODEL;
    srcs[1] = A1 + (size_t)bm * 128 * D_MODEL;
    srcs[2] = B0 + (size_t)bn * 64 * D_MODEL;
    srcs[3] = B1 + (size_t)bn * 64 * D_MODEL;

    float acc[2][4][4];
#pragma unroll
    for (int i = 0; i < 2; i++)
#pragma unroll
        for (int j = 0; j < 4; j++)
#pragma unroll
            for (int v = 0; v < 4; v++) acc[i][j][v] = 0.f;

    const uint32_t a_l = (uint32_t)(wm * 32 + (lane & 15)) * TLD + ((lane >> 4) & 1) * 16;
    const uint32_t b_l = (uint32_t)(wn * 32 + (lane & 7) + ((lane >> 4) & 1) * 8) * TLD
                       + ((lane >> 3) & 1) * 16;

    auto fill = [&](int c, int s) {
        const uint32_t base = sbase + (uint32_t)s * STAGE;
#pragma unroll
        for (int n = 0; n < 6; n++) {
            int i = tid + n * 256;
            bool isA = i < 1024;
            int j   = isA ? i : i - 1024;
            int lev = isA ? (j >> 9) : (j >> 8);
            int r   = isA ? ((j >> 2) & 127) : ((j >> 2) & 63);
            int c16 = j & 3;
            const unsigned short* src = srcs[(isA ? 0 : 2) + lev]
                + (size_t)r * D_MODEL + c * KC + c16 * 8;
            uint32_t dst = base + (isA ? (uint32_t)lev * AT_BYTES
                                       : 2u * AT_BYTES + (uint32_t)lev * BT_BYTES)
                         + (uint32_t)r * TLD + c16 * 16;
            cp16(dst, src);
        }
        asm volatile("cp.async.commit_group;" ::: "memory");
    };

    fill(0, 0);
    fill(1, 1);

    constexpr int PA[4] = { 0, 0, 1, 1 };
    constexpr int PB[4] = { 0, 1, 0, 1 };

    int stage = 0;
    for (int c = 0; c < NCHUNK; c++) {
        if (c + 1 < NCHUNK)
            asm volatile("cp.async.wait_group 1;" ::: "memory");
        else
            asm volatile("cp.async.wait_group 0;" ::: "memory");
        __syncthreads();                        // single barrier per chunk

        if (c + 2 < NCHUNK) {
            int fs = stage + 2; if (fs >= 3) fs -= 3;
            fill(c + 2, fs);                    // overwrites stage consumed at c-1
        }

        const uint32_t abase = sbase + (uint32_t)stage * STAGE;
        const uint32_t bbase = abase + 2 * AT_BYTES;

#pragma unroll
        for (int kb = 0; kb < 2; kb++) {
            const uint32_t kbyte = kb * 32;
            uint32_t af[2][2][4], bfr[2][2][4];
#pragma unroll
            for (int lv = 0; lv < 2; lv++) {
#pragma unroll
                for (int mt = 0; mt < 2; mt++)
                    ldsm_x4(af[lv][mt], abase + lv * AT_BYTES + a_l + mt * (16 * TLD) + kbyte);
#pragma unroll
                for (int np = 0; np < 2; np++)
                    ldsm_x4(bfr[lv][np], bbase + lv * BT_BYTES + b_l + np * (16 * TLD) + kbyte);
            }
#pragma unroll
            for (int p = 0; p < NPASS; p++) {
#pragma unroll
                for (int mt = 0; mt < 2; mt++)
#pragma unroll
                    for (int nt = 0; nt < 4; nt++)
                        mma_f16(acc[mt][nt], af[PA[p]][mt],
                                &bfr[PB[p]][nt >> 1][(nt & 1) * 2]);
            }
        }
        if (++stage == 3) stage = 0;
    }

    // epilogue: + bias; either fp32 C or fp16 h/l split (same arithmetic as split2h)
    const int qr = lane >> 2;
#pragma unroll
    for (int mt = 0; mt < 2; mt++) {
        int row0 = bm * 128 + wm * 32 + mt * 16 + qr;
#pragma unroll
        for (int nt = 0; nt < 4; nt++) {
            int col = bn * 64 + wn * 32 + nt * 8 + (lane & 3) * 2;
            float v00 = acc[mt][nt][0] + bias[col];
            float v01 = acc[mt][nt][1] + bias[col + 1];
            float v10 = acc[mt][nt][2] + bias[col];
            float v11 = acc[mt][nt][3] + bias[col + 1];
            if (SPLIT_OUT) {
                float dummy;
                ushort2 h0 = split_h(v00, dummy), h1 = split_h(v01, dummy);
                ushort2 h2 = split_h(v10, dummy), h3 = split_h(v11, dummy);
                *(ushort2*)(H + (size_t)row0 * D_MODEL + col)       = make_ushort2(h0.x, h1.x);
                *(ushort2*)(L + (size_t)row0 * D_MODEL + col)       = make_ushort2(h0.y, h1.y);
                *(ushort2*)(H + (size_t)(row0 + 8) * D_MODEL + col) = make_ushort2(h2.x, h3.x);
                *(ushort2*)(L + (size_t)(row0 + 8) * D_MODEL + col) = make_ushort2(h2.y, h3.y);
            } else {
                float2 v0 = { v00, v01 }, v1 = { v10, v11 };
                *(float2*)(C + (size_t)row0 * D_MODEL + col)       = v0;
                *(float2*)(C + (size_t)(row0 + 8) * D_MODEL + col) = v1;
            }
        }
    }
}

// =================================================================================
// mma attention: CTA = (b, h, 32 q-rows), 256 thr. O epilogue emits ctx h/l split.
// =================================================================================
#define PS_LD     1032
#define PS_BYTES  (32 * PS_LD * 4)       // 132096
#define KROWB     144
#define KLEV      (128 * KROWB)
#define KSTG      (2 * KLEV)             // 36864
#define VROWB     272
#define VLEV      (64 * VROWB)
#define VSTG      (2 * VLEV)             // 34816
#define ATTN_SMEM (PS_BYTES + 2 * KSTG)  // 205824

__global__ __launch_bounds__(256) void attn_mma(
    const unsigned char* __restrict__ mask, float* __restrict__ attn_out,
    const unsigned short* __restrict__ Q0, const unsigned short* __restrict__ Q1,
    unsigned short* __restrict__ C0, unsigned short* __restrict__ C1)
{
    extern __shared__ char smraw[];
    float* Ps = (float*)smraw;
    const uint32_t tbase = smem_u32(smraw) + PS_BYTES;

    const int t = threadIdx.x, w = t >> 5, lane = t & 31;
    const int qt = blockIdx.x, h = blockIdx.y, b = blockIdx.z;
    const int q0 = qt * 32;

    // ---- Q a-fragments from global ----
    uint32_t af[2][2][4][4];
    {
        const unsigned short* qs[2] = { Q0, Q1 };
        const int r0 = lane >> 2;
        const int c0 = (lane & 3) * 2;
#pragma unroll
        for (int lv = 0; lv < 2; lv++)
#pragma unroll
            for (int mt = 0; mt < 2; mt++)
#pragma unroll
                for (int ks = 0; ks < 4; ks++) {
                    size_t base = (size_t)(b * SEQ + q0 + mt * 16 + r0) * D_MODEL
                                + h * DKH + ks * 16 + c0;
                    af[lv][mt][ks][0] = *(const uint32_t*)(qs[lv] + base);
                    af[lv][mt][ks][1] = *(const uint32_t*)(qs[lv] + base + 8 * D_MODEL);
                    af[lv][mt][ks][2] = *(const uint32_t*)(qs[lv] + base + 8);
                    af[lv][mt][ks][3] = *(const uint32_t*)(qs[lv] + base + 8 * D_MODEL + 8);
                }
    }

    // ---- score phase ----
    auto kfill = [&](int kt, int s) {
#pragma unroll
        for (int n = 0; n < 8; n++) {
            int i = t + n * 256;
            int lv = i >> 10, j = i & 1023;
            int r = j >> 3, u = j & 7;
            const unsigned short* src = (lv ? g_k1s : g_k0s)
                + (size_t)(b * SEQ + kt * 128 + r) * D_MODEL + h * DKH + u * 8;
            cp16(tbase + s * KSTG + lv * KLEV + (uint32_t)r * KROWB + u * 16, src);
        }
        asm volatile("cp.async.commit_group;" ::: "memory");
    };
    const uint32_t krow = (uint32_t)(w * 16 + (lane & 7) + ((lane >> 4) & 1) * 8) * KROWB
                        + ((lane >> 3) & 1) * 16;
    kfill(0, 0);
    kfill(1, 1);

    for (int kt = 0; kt < 8; kt++) {
        if (kt < 7) asm volatile("cp.async.wait_group 1;" ::: "memory");
        else        asm volatile("cp.async.wait_group 0;" ::: "memory");
        __syncthreads();
        const uint32_t kb = tbase + (kt & 1) * KSTG;

        uint32_t bf[2][4][4];
#pragma unroll
        for (int lv = 0; lv < 2; lv++)
#pragma unroll
            for (int ks = 0; ks < 4; ks++)
                ldsm_x4(bf[lv][ks], kb + lv * KLEV + krow + ks * 32);

        float acc[2][2][4];
#pragma unroll
        for (int i = 0; i < 2; i++)
#pragma unroll
            for (int j = 0; j < 2; j++)
#pragma unroll
                for (int v = 0; v < 4; v++) acc[i][j][v] = 0.f;

#pragma unroll
        for (int ks = 0; ks < 4; ks++) {
#pragma unroll
            for (int mt = 0; mt < 2; mt++)
#pragma unroll
                for (int nt = 0; nt < 2; nt++) {
                    mma_f16(acc[mt][nt], af[0][mt][ks], &bf[0][ks][nt * 2]);
                    mma_f16(acc[mt][nt], af[0][mt][ks], &bf[1][ks][nt * 2]);
                    mma_f16(acc[mt][nt], af[1][mt][ks], &bf[0][ks][nt * 2]);
                }
        }

#pragma unroll
        for (int mt = 0; mt < 2; mt++) {
#pragma unroll
            for (int nt = 0; nt < 2; nt++) {
                int row = mt * 16 + (lane >> 2);
                int col = kt * 128 + w * 16 + nt * 8 + (lane & 3) * 2;
                const unsigned char* mp0 =
                    mask + (size_t)(b * SEQ + q0 + row) * SEQ + col;
                const unsigned char* mp1 = mp0 + 8 * SEQ;
                float2 v0, v1;
                v0.x = mp0[0] ? -1e9f : acc[mt][nt][0] * 0.125f;
                v0.y = mp0[1] ? -1e9f : acc[mt][nt][1] * 0.125f;
                v1.x = mp1[0] ? -1e9f : acc[mt][nt][2] * 0.125f;
                v1.y = mp1[1] ? -1e9f : acc[mt][nt][3] * 0.125f;
                *(float2*)&Ps[row * PS_LD + col]       = v0;
                *(float2*)&Ps[(row + 8) * PS_LD + col] = v1;
            }
        }
        __syncthreads();
        if (kt + 2 < 8) kfill(kt + 2, kt & 1);
    }
    __syncthreads();

    // ---- row softmax ----
    {
        int row = t >> 3, sub = t & 7;
        float* pr = Ps + row * PS_LD;
        float m = -1e30f;
        for (int cc = sub; cc < SEQ; cc += 8) m = fmaxf(m, pr[cc]);
#pragma unroll
        for (int o = 4; o > 0; o >>= 1) m = fmaxf(m, __shfl_xor_sync(0xffffffffu, m, o, 8));
        float s = 0.f;
        for (int cc = sub; cc < SEQ; cc += 8) { float e = __expf(pr[cc] - m); pr[cc] = e; s += e; }
#pragma unroll
        for (int o = 4; o > 0; o >>= 1) s += __shfl_xor_sync(0xffffffffu, s, o, 8);
        float inv = 1.0f / s;
        for (int cc = sub; cc < SEQ; cc += 8) pr[cc] *= inv;
    }
    __syncthreads();

    // ---- write attn ----
    if (attn_out) {
        float* ab = attn_out + (((size_t)(b * NHEAD + h)) * SEQ + q0) * SEQ;
#pragma unroll
        for (int i = 0; i < 32; i++) {
            int idx = t + i * 256;
            int r  = idx >> 8;
            int c4 = (idx & 255) << 2;
            *(float4*)&ab[(size_t)r * SEQ + c4] = *(const float4*)&Ps[r * PS_LD + c4];
        }
    }
    __syncthreads();

    // ---- PV phase ----
    auto vfill = [&](int kt, int s) {
#pragma unroll
        for (int n = 0; n < 8; n++) {
            int i = t + n * 256;
            int lv = i >> 10, j = i & 1023;
            int r = j >> 4, u = j & 15;
            const unsigned short* src = (lv ? g_v1t : g_v0t)
                + ((size_t)(b * NHEAD + h) * DKH + r) * SEQ + kt * 128 + u * 8;
            cp16(tbase + s * VSTG + lv * VLEV + (uint32_t)r * VROWB + u * 16, src);
        }
        asm volatile("cp.async.commit_group;" ::: "memory");
    };
    const int mh = w & 1, nq = w >> 1;
    const uint32_t vrow = (uint32_t)(nq * 16 + (lane & 7) + ((lane >> 4) & 1) * 8) * VROWB
                        + ((lane >> 3) & 1) * 16;
    float oacc[2][4];
#pragma unroll
    for (int i = 0; i < 2; i++)
#pragma unroll
        for (int v = 0; v < 4; v++) oacc[i][v] = 0.f;

    vfill(0, 0);
    vfill(1, 1);

    const int pr0 = mh * 16 + (lane >> 2);
    const int pc0 = (lane & 3) * 2;

    for (int kt = 0; kt < 8; kt++) {
        if (kt < 7) asm volatile("cp.async.wait_group 1;" ::: "memory");
        else        asm volatile("cp.async.wait_group 0;" ::: "memory");
        __syncthreads();
        const uint32_t vb = tbase + (kt & 1) * VSTG;

#pragma unroll
        for (int ks = 0; ks < 8; ks++) {
            uint32_t bv[2][4];
            ldsm_x4(bv[0], vb + vrow + ks * 32);
            ldsm_x4(bv[1], vb + VLEV + vrow + ks * 32);

            int pc = kt * 128 + ks * 16 + pc0;
            float2 p00 = *(float2*)&Ps[pr0 * PS_LD + pc];
            float2 p10 = *(float2*)&Ps[(pr0 + 8) * PS_LD + pc];
            float2 p01 = *(float2*)&Ps[pr0 * PS_LD + pc + 8];
            float2 p11 = *(float2*)&Ps[(pr0 + 8) * PS_LD + pc + 8];

            uint32_t ph[4], pl[4];
            {
                __half2 h0 = __floats2half2_rn(p00.x, p00.y);
                __half2 h1 = __floats2half2_rn(p10.x, p10.y);
                __half2 h2 = __floats2half2_rn(p01.x, p01.y);
                __half2 h3 = __floats2half2_rn(p11.x, p11.y);
                ph[0] = *(uint32_t*)&h0; ph[1] = *(uint32_t*)&h1;
                ph[2] = *(uint32_t*)&h2; ph[3] = *(uint32_t*)&h3;
                float2 f0 = __half22float2(h0), f1 = __half22float2(h1);
                float2 f2 = __half22float2(h2), f3 = __half22float2(h3);
                __half2 l0 = __floats2half2_rn(p00.x - f0.x, p00.y - f0.y);
                __half2 l1 = __floats2half2_rn(p10.x - f1.x, p10.y - f1.y);
                __half2 l2 = __floats2half2_rn(p01.x - f2.x, p01.y - f2.y);
                __half2 l3 = __floats2half2_rn(p11.x - f3.x, p11.y - f3.y);
                pl[0] = *(uint32_t*)&l0; pl[1] = *(uint32_t*)&l1;
                pl[2] = *(uint32_t*)&l2; pl[3] = *(uint32_t*)&l3;
            }
            mma_f16(oacc[0], ph, &bv[0][0]);
            mma_f16(oacc[1], ph, &bv[0][2]);
            mma_f16(oacc[0], ph, &bv[1][0]);
            mma_f16(oacc[1], ph, &bv[1][2]);
            mma_f16(oacc[0], pl, &bv[0][0]);
            mma_f16(oacc[1], pl, &bv[0][2]);
        }
        __syncthreads();
        if (kt + 2 < 8) vfill(kt + 2, kt & 1);
    }

    // ---- write O split directly (ctx h/l) ----
    {
        int orow = b * SEQ + q0 + pr0;
        int ocol = h * DKH + nq * 16 + pc0;
#pragma unroll
        for (int nt = 0; nt < 2; nt++) {
            float dummy;
            ushort2 s0 = split_h(oacc[nt][0], dummy), s1 = split_h(oacc[nt][1], dummy);
            ushort2 s2 = split_h(oacc[nt][2], dummy), s3 = split_h(oacc[nt][3], dummy);
            *(ushort2*)&C0[(size_t)orow * D_MODEL + ocol + nt * 8]       = make_ushort2(s0.x, s1.x);
            *(ushort2*)&C1[(size_t)orow * D_MODEL + ocol + nt * 8]       = make_ushort2(s0.y, s1.y);
            *(ushort2*)&C0[(size_t)(orow + 8) * D_MODEL + ocol + nt * 8] = make_ushort2(s2.x, s3.x);
            *(ushort2*)&C1[(size_t)(orow + 8) * D_MODEL + ocol + nt * 8] = make_ushort2(s2.y, s3.y);
        }
    }
}

// =================================================================================
// Residual add + LayerNorm
// =================================================================================
__global__ __launch_bounds__(256) void ln_kernel(
    const float* __restrict__ fc, const float* __restrict__ resid,
    const float* __restrict__ gamma, const float* __restrict__ beta,
    float* __restrict__ out)
{
    __shared__ float xs[D_MODEL];
    __shared__ float rs[8], rss[8];

    const int row = blockIdx.x;
    const int t   = threadIdx.x;
    const float* f = fc    + (size_t)row * D_MODEL;
    const float* r = resid + (size_t)row * D_MODEL;

    float s = 0.f, ss = 0.f;
    for (int i = t; i < D_MODEL; i += 256) {
        float x = f[i] + r[i];
        xs[i] = x;
        s += x; ss += x * x;
    }
#pragma unroll
    for (int o = 16; o > 0; o >>= 1) {
        s  += __shfl_xor_sync(0xffffffffu, s, o);
        ss += __shfl_xor_sync(0xffffffffu, ss, o);
    }
    int w = t >> 5, lane = t & 31;
    if (lane == 0) { rs[w] = s; rss[w] = ss; }
    __syncthreads();
    float ts = 0.f, tss = 0.f;
#pragma unroll
    for (int i = 0; i < 8; i++) { ts += rs[i]; tss += rss[i]; }
    float mu  = ts * (1.0f / D_MODEL);
    float var = tss * (1.0f / D_MODEL) - mu * mu;
    float kk  = rsqrtf(var + 1e-5f);

    for (int i = t; i < D_MODEL; i += 256)
        out[(size_t)row * D_MODEL + i] = (xs[i] - mu) * kk * gamma[i] + beta[i];
}

// =================================================================================
// launch
// =================================================================================
extern "C" void kernel_launch(void* const* d_in, const int* in_sizes, int n_in,
                              void* d_out, int out_size)
{
    const float* q    = (const float*)d_in[0];
    const float* k    = (const float*)d_in[1];
    const float* v    = (const float*)d_in[2];
    const unsigned char* mask = (const unsigned char*)d_in[3];
    const float* w_q  = (const float*)d_in[4];
    const float* b_q  = (const float*)d_in[5];
    const float* w_k  = (const float*)d_in[6];
    const float* b_k  = (const float*)d_in[7];
    const float* w_v  = (const float*)d_in[8];
    const float* b_v  = (const float*)d_in[9];
    const float* w_fc = (const float*)d_in[10];
    const float* b_fc = (const float*)d_in[11];
    const float* ln_g = (const float*)d_in[12];
    const float* ln_b = (const float*)d_in[13];
    float* out = (float*)d_out;

    float *qh, *vh, *ctx, *fc;
    unsigned short *a0, *a1, *b0, *b1, *k0s, *k1s;
    cudaGetSymbolAddress((void**)&qh,  g_qh);
    cudaGetSymbolAddress((void**)&vh,  g_vh);
    cudaGetSymbolAddress((void**)&ctx, g_ctx);
    cudaGetSymbolAddress((void**)&fc,  g_fc);
    cudaGetSymbolAddress((void**)&a0,  g_a0);
    cudaGetSymbolAddress((void**)&a1,  g_a1);
    cudaGetSymbolAddress((void**)&b0,  g_b0);
    cudaGetSymbolAddress((void**)&b1,  g_b1);
    cudaGetSymbolAddress((void**)&k0s, g_k0s);
    cudaGetSymbolAddress((void**)&k1s, g_k1s);

    // carve split buffers out of the now-unneeded fp32 scratch
    unsigned short* q0s = (unsigned short*)qh;
    unsigned short* q1s = q0s + (size_t)MROWS * D_MODEL;
    unsigned short* c0s = (unsigned short*)ctx;
    unsigned short* c1s = c0s + (size_t)MROWS * D_MODEL;

    const long long xe = (long long)MROWS * D_MODEL;
    const long long ae = (long long)BATCH * NHEAD * SEQ * SEQ;
    float* attn_out = nullptr;
    float* x_out    = out;
    if ((long long)out_size >= xe + ae) {
        attn_out = out + xe;
    } else if ((long long)out_size == ae) {
        attn_out = out;
        x_out = nullptr;
    }

    cudaFuncSetAttribute((void*)gemm_2h<4, true>,  cudaFuncAttributeMaxDynamicSharedMemorySize, GSMEM3);
    cudaFuncSetAttribute((void*)gemm_2h<3, false>, cudaFuncAttributeMaxDynamicSharedMemorySize, GSMEM3);
    cudaFuncSetAttribute((void*)attn_mma, cudaFuncAttributeMaxDynamicSharedMemorySize, ATTN_SMEM);

    const int nA4 = MROWS * D_MODEL / 4;
    const int nW4 = D_MODEL * D_MODEL / 4;
    dim3 gb(256);
    dim3 gg(D_MODEL / 64, MROWS / 128);    // (16, 64)

    // Q projection -> split output directly
    split2h_kernel<<<nA4 / 256, gb>>>(q, a0, a1, nA4);
    split2h_kernel<<<nW4 / 256, gb>>>(w_q, b0, b1, nW4);
    gemm_2h<4, true><<<gg, gb, GSMEM3>>>(a0, a1, b0, b1, b_q, nullptr, q0s, q1s);

    // K projection -> split output directly
    split2h_kernel<<<nA4 / 256, gb>>>(k, a0, a1, nA4);
    split2h_kernel<<<nW4 / 256, gb>>>(w_k, b0, b1, nW4);
    gemm_2h<4, true><<<gg, gb, GSMEM3>>>(a0, a1, b0, b1, b_k, nullptr, k0s, k1s);

    // V projection -> fp32 (vtrans consumes it)
    split2h_kernel<<<nA4 / 256, gb>>>(v, a0, a1, nA4);
    split2h_kernel<<<nW4 / 256, gb>>>(w_v, b0, b1, nW4);
    gemm_2h<3, false><<<gg, gb, GSMEM3>>>(a0, a1, b0, b1, b_v, vh, nullptr, nullptr);

    vtrans_kernel<<<dim3(SEQ / 32, DKH / 32, BATCH * NHEAD), dim3(32, 8)>>>();

    dim3 ag(SEQ / 32, NHEAD, BATCH);
    attn_mma<<<ag, gb, ATTN_SMEM>>>(mask, attn_out, q0s, q1s, c0s, c1s);

    // FC (ctx split produced by attention epilogue)
    split2h_kernel<<<nW4 / 256, gb>>>(w_fc, b0, b1, nW4);
    gemm_2h<3, false><<<gg, gb, GSMEM3>>>(c0s, c1s, b0, b1, b_fc, fc, nullptr, nullptr);

    if (x_out)
        ln_kernel<<<MROWS, gb>>>(fc, q, ln_g, ln_b, x_out);
}

// round 9
// speedup vs baseline: 2.3223x; 1.0343x over previous
#include <cuda_runtime.h>
#include <cuda_fp16.h>
#include <cstdint>
#include <cstddef>

#define D_MODEL 1024
#define NHEAD   16
#define DKH     64
#define BATCH   8
#define SEQ     1024
#define MROWS   (BATCH * SEQ)   // 8192

// ---------------- scratch (device globals: no cudaMalloc allowed) ----------------
__device__ float g_qh[MROWS * D_MODEL];    // carved as Q h/l split (ushort x2)
__device__ float g_vh[MROWS * D_MODEL];    // fp32 V (for vtrans)
__device__ float g_ctx[MROWS * D_MODEL];   // carved as ctx h/l split (ushort x2)
__device__ float g_fc[MROWS * D_MODEL];
// fp16 2-level split operands
__device__ __align__(16) unsigned short g_a0[MROWS * D_MODEL];
__device__ __align__(16) unsigned short g_a1[MROWS * D_MODEL];
__device__ __align__(16) unsigned short g_b0[D_MODEL * D_MODEL];
__device__ __align__(16) unsigned short g_b1[D_MODEL * D_MODEL];
__device__ __align__(16) unsigned short g_k0s[MROWS * D_MODEL];
__device__ __align__(16) unsigned short g_k1s[MROWS * D_MODEL];
__device__ __align__(16) unsigned short g_v0t[MROWS * D_MODEL];   // [bh][d][token]
__device__ __align__(16) unsigned short g_v1t[MROWS * D_MODEL];

// =================================================================================
// helpers
// =================================================================================
__device__ __forceinline__ uint32_t smem_u32(const void* p) {
    uint32_t a;
    asm("{ .reg .u64 t; cvta.to.shared.u64 t, %1; cvt.u32.u64 %0, t; }" : "=r"(a) : "l"(p));
    return a;
}
__device__ __forceinline__ void ldsm_x4(uint32_t* r, uint32_t addr) {
    asm volatile("ldmatrix.sync.aligned.m8n8.x4.shared.b16 {%0,%1,%2,%3}, [%4];"
        : "=r"(r[0]), "=r"(r[1]), "=r"(r[2]), "=r"(r[3]) : "r"(addr));
}
__device__ __forceinline__ void mma_f16(float* c, const uint32_t* a, const uint32_t* b) {
    asm volatile("mma.sync.aligned.m16n8k16.row.col.f32.f16.f16.f32 "
        "{%0,%1,%2,%3}, {%4,%5,%6,%7}, {%8,%9}, {%0,%1,%2,%3};"
        : "+f"(c[0]), "+f"(c[1]), "+f"(c[2]), "+f"(c[3])
        : "r"(a[0]), "r"(a[1]), "r"(a[2]), "r"(a[3]), "r"(b[0]), "r"(b[1]));
}
__device__ __forceinline__ void cp16(uint32_t dst, const void* src) {
    asm volatile("cp.async.cg.shared.global [%0], [%1], 16;" :: "r"(dst), "l"(src));
}
__device__ __forceinline__ ushort2 split_h(float x, float& rem) {
    __half hb = __float2half_rn(x);
    float hf = __half2float(hb);
    __half lb = __float2half_rn(x - hf);
    rem = 0.f;
    return make_ushort2(__half_as_ushort(hb), __half_as_ushort(lb));
}

// =================================================================================
// fp32 -> fp16 2-level split (standalone, for raw inputs / weights)
// =================================================================================
__global__ __launch_bounds__(256) void split2h_kernel(
    const float* __restrict__ x, unsigned short* __restrict__ h,
    unsigned short* __restrict__ l, int n4)
{
    int i = blockIdx.x * 256 + threadIdx.x;
    if (i >= n4) return;
    float4 v = ((const float4*)x)[i];
    float vv[4] = { v.x, v.y, v.z, v.w };
    unsigned short hh[4], ll[4];
#pragma unroll
    for (int j = 0; j < 4; j++) {
        __half hb = __float2half_rn(vv[j]);
        float r1 = vv[j] - __half2float(hb);
        __half lb = __float2half_rn(r1);
        hh[j] = __half_as_ushort(hb);
        ll[j] = __half_as_ushort(lb);
    }
    ((ushort4*)h)[i] = make_ushort4(hh[0], hh[1], hh[2], hh[3]);
    ((ushort4*)l)[i] = make_ushort4(ll[0], ll[1], ll[2], ll[3]);
}

// =================================================================================
// V transpose + split:  g_vh[token][h*64+d] -> g_v{0,1}t[(bh*64+d)*1024 + token]
// =================================================================================
__global__ __launch_bounds__(256) void vtrans_kernel()
{
    __shared__ float ttile[32][33];
    const int bh = blockIdx.z, b = bh >> 4, h = bh & 15;
    const int t0 = blockIdx.x * 32, d0 = blockIdx.y * 32;
    const int tx = threadIdx.x, ty = threadIdx.y;
#pragma unroll
    for (int j = 0; j < 4; j++) {
        int tok = t0 + ty + j * 8;
        ttile[ty + j * 8][tx] =
            g_vh[(size_t)(b * SEQ + tok) * D_MODEL + h * DKH + d0 + tx];
    }
    __syncthreads();
#pragma unroll
    for (int j = 0; j < 4; j++) {
        int d = d0 + ty + j * 8;
        float x = ttile[tx][ty + j * 8];
        __half hb = __float2half_rn(x);
        __half lb = __float2half_rn(x - __half2float(hb));
        size_t o = ((size_t)bh * DKH + d) * SEQ + t0 + tx;
        g_v0t[o] = __half_as_ushort(hb);
        g_v1t[o] = __half_as_ushort(lb);
    }
}

// =================================================================================
// 2-level fp16 mma GEMM, 3-stage cp.async ring, one sync per chunk.
// CTA tile 128x64, 8 warps (4m x 2n), warp tile 32x32, KC=32, 2 CTAs/SM.
// NPASS=3: hh,hl,lh (2^-22). NPASS=4 adds ll (2^-23).
// SPLIT_OUT: epilogue emits fp16 h/l split directly (no fp32 C).
// =================================================================================
#define KC         32
#define NCHUNK     (D_MODEL / KC)
#define TLD        80
#define AT_BYTES   (128 * TLD)
#define BT_BYTES   (64 * TLD)
#define STAGE      (2 * AT_BYTES + 2 * BT_BYTES)   // 30720
#define GSMEM3     (3 * STAGE)                     // 92160

template<int NPASS, bool SPLIT_OUT>
__global__ void __launch_bounds__(256, 2) gemm_2h(
    const unsigned short* __restrict__ A0, const unsigned short* __restrict__ A1,
    const unsigned short* __restrict__ B0, const unsigned short* __restrict__ B1,
    const float* __restrict__ bias,
    float* __restrict__ C,
    unsigned short* __restrict__ H, unsigned short* __restrict__ L)
{
    extern __shared__ char smc[];
    const uint32_t sbase = smem_u32(smc);
    const int tid = threadIdx.x, wid = tid >> 5, lane = tid & 31;
    const int bn = blockIdx.x, bm = blockIdx.y;
    const int wm = wid & 3, wn = wid >> 2;

    const unsigned short* srcs[4];
    srcs[0] = A0 + (size_t)bm * 128 * D_MODEL;
    srcs[1] = A1 + (size_t)bm * 128 * D_MODEL;
    srcs[2] = B0 + (size_t)bn * 64 * D_MODEL;
    srcs[3] = B1 + (size_t)bn * 64 * D_MODEL;

    float acc[2][4][4];
#pragma unroll
    for (int i = 0; i < 2; i++)
#pragma unroll
        for (int j = 0; j < 4; j++)
#pragma unroll
            for (int v = 0; v < 4; v++) acc[i][j][v] = 0.f;

    const uint32_t a_l = (uint32_t)(wm * 32 + (lane & 15)) * TLD + ((lane >> 4) & 1) * 16;
    const uint32_t b_l = (uint32_t)(wn * 32 + (lane & 7) + ((lane >> 4) & 1) * 8) * TLD
                       + ((lane >> 3) & 1) * 16;

    auto fill = [&](int c, int s) {
        const uint32_t base = sbase + (uint32_t)s * STAGE;
#pragma unroll
        for (int n = 0; n < 6; n++) {
            int i = tid + n * 256;
            bool isA = i < 1024;
            int j   = isA ? i : i - 1024;
            int lev = isA ? (j >> 9) : (j >> 8);
            int r   = isA ? ((j >> 2) & 127) : ((j >> 2) & 63);
            int c16 = j & 3;
            const unsigned short* src = srcs[(isA ? 0 : 2) + lev]
                + (size_t)r * D_MODEL + c * KC + c16 * 8;
            uint32_t dst = base + (isA ? (uint32_t)lev * AT_BYTES
                                       : 2u * AT_BYTES + (uint32_t)lev * BT_BYTES)
                         + (uint32_t)r * TLD + c16 * 16;
            cp16(dst, src);
        }
        asm volatile("cp.async.commit_group;" ::: "memory");
    };

    fill(0, 0);
    fill(1, 1);

    constexpr int PA[4] = { 0, 0, 1, 1 };
    constexpr int PB[4] = { 0, 1, 0, 1 };

    int stage = 0;
    for (int c = 0; c < NCHUNK; c++) {
        if (c + 1 < NCHUNK)
            asm volatile("cp.async.wait_group 1;" ::: "memory");
        else
            asm volatile("cp.async.wait_group 0;" ::: "memory");
        __syncthreads();

        if (c + 2 < NCHUNK) {
            int fs = stage + 2; if (fs >= 3) fs -= 3;
            fill(c + 2, fs);
        }

        const uint32_t abase = sbase + (uint32_t)stage * STAGE;
        const uint32_t bbase = abase + 2 * AT_BYTES;

#pragma unroll
        for (int kb = 0; kb < 2; kb++) {
            const uint32_t kbyte = kb * 32;
            uint32_t af[2][2][4], bfr[2][2][4];
#pragma unroll
            for (int lv = 0; lv < 2; lv++) {
#pragma unroll
                for (int mt = 0; mt < 2; mt++)
                    ldsm_x4(af[lv][mt], abase + lv * AT_BYTES + a_l + mt * (16 * TLD) + kbyte);
#pragma unroll
                for (int np = 0; np < 2; np++)
                    ldsm_x4(bfr[lv][np], bbase + lv * BT_BYTES + b_l + np * (16 * TLD) + kbyte);
            }
#pragma unroll
            for (int p = 0; p < NPASS; p++) {
#pragma unroll
                for (int mt = 0; mt < 2; mt++)
#pragma unroll
                    for (int nt = 0; nt < 4; nt++)
                        mma_f16(acc[mt][nt], af[PA[p]][mt],
                                &bfr[PB[p]][nt >> 1][(nt & 1) * 2]);
            }
        }
        if (++stage == 3) stage = 0;
    }

    // epilogue: + bias; either fp32 C or fp16 h/l split (same arithmetic as split2h)
    const int qr = lane >> 2;
#pragma unroll
    for (int mt = 0; mt < 2; mt++) {
        int row0 = bm * 128 + wm * 32 + mt * 16 + qr;
#pragma unroll
        for (int nt = 0; nt < 4; nt++) {
            int col = bn * 64 + wn * 32 + nt * 8 + (lane & 3) * 2;
            float v00 = acc[mt][nt][0] + bias[col];
            float v01 = acc[mt][nt][1] + bias[col + 1];
            float v10 = acc[mt][nt][2] + bias[col];
            float v11 = acc[mt][nt][3] + bias[col + 1];
            if (SPLIT_OUT) {
                float dummy;
                ushort2 h0 = split_h(v00, dummy), h1 = split_h(v01, dummy);
                ushort2 h2 = split_h(v10, dummy), h3 = split_h(v11, dummy);
                *(ushort2*)(H + (size_t)row0 * D_MODEL + col)       = make_ushort2(h0.x, h1.x);
                *(ushort2*)(L + (size_t)row0 * D_MODEL + col)       = make_ushort2(h0.y, h1.y);
                *(ushort2*)(H + (size_t)(row0 + 8) * D_MODEL + col) = make_ushort2(h2.x, h3.x);
                *(ushort2*)(L + (size_t)(row0 + 8) * D_MODEL + col) = make_ushort2(h2.y, h3.y);
            } else {
                float2 v0 = { v00, v01 }, v1 = { v10, v11 };
                *(float2*)(C + (size_t)row0 * D_MODEL + col)       = v0;
                *(float2*)(C + (size_t)(row0 + 8) * D_MODEL + col) = v1;
            }
        }
    }
}

// =================================================================================
// mma attention: CTA = (b, h, 32 q-rows), 256 thr. O epilogue emits ctx h/l split.
// =================================================================================
#define PS_LD     1032
#define PS_BYTES  (32 * PS_LD * 4)       // 132096
#define KROWB     144
#define KLEV      (128 * KROWB)
#define KSTG      (2 * KLEV)             // 36864
#define VROWB     272
#define VLEV      (64 * VROWB)
#define VSTG      (2 * VLEV)             // 34816
#define ATTN_SMEM (PS_BYTES + 2 * KSTG)  // 205824

__global__ __launch_bounds__(256) void attn_mma(
    const unsigned char* __restrict__ mask, float* __restrict__ attn_out,
    const unsigned short* __restrict__ Q0, const unsigned short* __restrict__ Q1,
    unsigned short* __restrict__ C0, unsigned short* __restrict__ C1)
{
    extern __shared__ char smraw[];
    float* Ps = (float*)smraw;
    const uint32_t tbase = smem_u32(smraw) + PS_BYTES;

    const int t = threadIdx.x, w = t >> 5, lane = t & 31;
    const int qt = blockIdx.x, h = blockIdx.y, b = blockIdx.z;
    const int q0 = qt * 32;

    // ---- Q a-fragments from global ----
    uint32_t af[2][2][4][4];
    {
        const unsigned short* qs[2] = { Q0, Q1 };
        const int r0 = lane >> 2;
        const int c0 = (lane & 3) * 2;
#pragma unroll
        for (int lv = 0; lv < 2; lv++)
#pragma unroll
            for (int mt = 0; mt < 2; mt++)
#pragma unroll
                for (int ks = 0; ks < 4; ks++) {
                    size_t base = (size_t)(b * SEQ + q0 + mt * 16 + r0) * D_MODEL
                                + h * DKH + ks * 16 + c0;
                    af[lv][mt][ks][0] = *(const uint32_t*)(qs[lv] + base);
                    af[lv][mt][ks][1] = *(const uint32_t*)(qs[lv] + base + 8 * D_MODEL);
                    af[lv][mt][ks][2] = *(const uint32_t*)(qs[lv] + base + 8);
                    af[lv][mt][ks][3] = *(const uint32_t*)(qs[lv] + base + 8 * D_MODEL + 8);
                }
    }

    // ---- score phase ----
    auto kfill = [&](int kt, int s) {
#pragma unroll
        for (int n = 0; n < 8; n++) {
            int i = t + n * 256;
            int lv = i >> 10, j = i & 1023;
            int r = j >> 3, u = j & 7;
            const unsigned short* src = (lv ? g_k1s : g_k0s)
                + (size_t)(b * SEQ + kt * 128 + r) * D_MODEL + h * DKH + u * 8;
            cp16(tbase + s * KSTG + lv * KLEV + (uint32_t)r * KROWB + u * 16, src);
        }
        asm volatile("cp.async.commit_group;" ::: "memory");
    };
    const uint32_t krow = (uint32_t)(w * 16 + (lane & 7) + ((lane >> 4) & 1) * 8) * KROWB
                        + ((lane >> 3) & 1) * 16;
    kfill(0, 0);
    kfill(1, 1);

    for (int kt = 0; kt < 8; kt++) {
        if (kt < 7) asm volatile("cp.async.wait_group 1;" ::: "memory");
        else        asm volatile("cp.async.wait_group 0;" ::: "memory");
        __syncthreads();
        const uint32_t kb = tbase + (kt & 1) * KSTG;

        uint32_t bf[2][4][4];
#pragma unroll
        for (int lv = 0; lv < 2; lv++)
#pragma unroll
            for (int ks = 0; ks < 4; ks++)
                ldsm_x4(bf[lv][ks], kb + lv * KLEV + krow + ks * 32);

        float acc[2][2][4];
#pragma unroll
        for (int i = 0; i < 2; i++)
#pragma unroll
            for (int j = 0; j < 2; j++)
#pragma unroll
                for (int v = 0; v < 4; v++) acc[i][j][v] = 0.f;

#pragma unroll
        for (int ks = 0; ks < 4; ks++) {
#pragma unroll
            for (int mt = 0; mt < 2; mt++)
#pragma unroll
                for (int nt = 0; nt < 2; nt++) {
                    mma_f16(acc[mt][nt], af[0][mt][ks], &bf[0][ks][nt * 2]);
                    mma_f16(acc[mt][nt], af[0][mt][ks], &bf[1][ks][nt * 2]);
                    mma_f16(acc[mt][nt], af[1][mt][ks], &bf[0][ks][nt * 2]);
                }
        }

#pragma unroll
        for (int mt = 0; mt < 2; mt++) {
#pragma unroll
            for (int nt = 0; nt < 2; nt++) {
                int row = mt * 16 + (lane >> 2);
                int col = kt * 128 + w * 16 + nt * 8 + (lane & 3) * 2;
                const unsigned char* mp0 =
                    mask + (size_t)(b * SEQ + q0 + row) * SEQ + col;
                const unsigned char* mp1 = mp0 + 8 * SEQ;
                float2 v0, v1;
                v0.x = mp0[0] ? -1e9f : acc[mt][nt][0] * 0.125f;
                v0.y = mp0[1] ? -1e9f : acc[mt][nt][1] * 0.125f;
                v1.x = mp1[0] ? -1e9f : acc[mt][nt][2] * 0.125f;
                v1.y = mp1[1] ? -1e9f : acc[mt][nt][3] * 0.125f;
                *(float2*)&Ps[row * PS_LD + col]       = v0;
                *(float2*)&Ps[(row + 8) * PS_LD + col] = v1;
            }
        }
        __syncthreads();
        if (kt + 2 < 8) kfill(kt + 2, kt & 1);
    }
    __syncthreads();

    // ---- row softmax ----
    {
        int row = t >> 3, sub = t & 7;
        float* pr = Ps + row * PS_LD;
        float m = -1e30f;
        for (int cc = sub; cc < SEQ; cc += 8) m = fmaxf(m, pr[cc]);
#pragma unroll
        for (int o = 4; o > 0; o >>= 1) m = fmaxf(m, __shfl_xor_sync(0xffffffffu, m, o, 8));
        float s = 0.f;
        for (int cc = sub; cc < SEQ; cc += 8) { float e = __expf(pr[cc] - m); pr[cc] = e; s += e; }
#pragma unroll
        for (int o = 4; o > 0; o >>= 1) s += __shfl_xor_sync(0xffffffffu, s, o, 8);
        float inv = 1.0f / s;
        for (int cc = sub; cc < SEQ; cc += 8) pr[cc] *= inv;
    }
    __syncthreads();

    // ---- write attn ----
    if (attn_out) {
        float* ab = attn_out + (((size_t)(b * NHEAD + h)) * SEQ + q0) * SEQ;
#pragma unroll
        for (int i = 0; i < 32; i++) {
            int idx = t + i * 256;
            int r  = idx >> 8;
            int c4 = (idx & 255) << 2;
            *(float4*)&ab[(size_t)r * SEQ + c4] = *(const float4*)&Ps[r * PS_LD + c4];
        }
    }
    __syncthreads();

    // ---- PV phase ----
    auto vfill = [&](int kt, int s) {
#pragma unroll
        for (int n = 0; n < 8; n++) {
            int i = t + n * 256;
            int lv = i >> 10, j = i & 1023;
            int r = j >> 4, u = j & 15;
            const unsigned short* src = (lv ? g_v1t : g_v0t)
                + ((size_t)(b * NHEAD + h) * DKH + r) * SEQ + kt * 128 + u * 8;
            cp16(tbase + s * VSTG + lv * VLEV + (uint32_t)r * VROWB + u * 16, src);
        }
        asm volatile("cp.async.commit_group;" ::: "memory");
    };
    const int mh = w & 1, nq = w >> 1;
    const uint32_t vrow = (uint32_t)(nq * 16 + (lane & 7) + ((lane >> 4) & 1) * 8) * VROWB
                        + ((lane >> 3) & 1) * 16;
    float oacc[2][4];
#pragma unroll
    for (int i = 0; i < 2; i++)
#pragma unroll
        for (int v = 0; v < 4; v++) oacc[i][v] = 0.f;

    vfill(0, 0);
    vfill(1, 1);

    const int pr0 = mh * 16 + (lane >> 2);
    const int pc0 = (lane & 3) * 2;

    for (int kt = 0; kt < 8; kt++) {
        if (kt < 7) asm volatile("cp.async.wait_group 1;" ::: "memory");
        else        asm volatile("cp.async.wait_group 0;" ::: "memory");
        __syncthreads();
        const uint32_t vb = tbase + (kt & 1) * VSTG;

#pragma unroll
        for (int ks = 0; ks < 8; ks++) {
            uint32_t bv[2][4];
            ldsm_x4(bv[0], vb + vrow + ks * 32);
            ldsm_x4(bv[1], vb + VLEV + vrow + ks * 32);

            int pc = kt * 128 + ks * 16 + pc0;
            float2 p00 = *(float2*)&Ps[pr0 * PS_LD + pc];
            float2 p10 = *(float2*)&Ps[(pr0 + 8) * PS_LD + pc];
            float2 p01 = *(float2*)&Ps[pr0 * PS_LD + pc + 8];
            float2 p11 = *(float2*)&Ps[(pr0 + 8) * PS_LD + pc + 8];

            uint32_t ph[4], pl[4];
            {
                __half2 h0 = __floats2half2_rn(p00.x, p00.y);
                __half2 h1 = __floats2half2_rn(p10.x, p10.y);
                __half2 h2 = __floats2half2_rn(p01.x, p01.y);
                __half2 h3 = __floats2half2_rn(p11.x, p11.y);
                ph[0] = *(uint32_t*)&h0; ph[1] = *(uint32_t*)&h1;
                ph[2] = *(uint32_t*)&h2; ph[3] = *(uint32_t*)&h3;
                float2 f0 = __half22float2(h0), f1 = __half22float2(h1);
                float2 f2 = __half22float2(h2), f3 = __half22float2(h3);
                __half2 l0 = __floats2half2_rn(p00.x - f0.x, p00.y - f0.y);
                __half2 l1 = __floats2half2_rn(p10.x - f1.x, p10.y - f1.y);
                __half2 l2 = __floats2half2_rn(p01.x - f2.x, p01.y - f2.y);
                __half2 l3 = __floats2half2_rn(p11.x - f3.x, p11.y - f3.y);
                pl[0] = *(uint32_t*)&l0; pl[1] = *(uint32_t*)&l1;
                pl[2] = *(uint32_t*)&l2; pl[3] = *(uint32_t*)&l3;
            }
            mma_f16(oacc[0], ph, &bv[0][0]);
            mma_f16(oacc[1], ph, &bv[0][2]);
            mma_f16(oacc[0], ph, &bv[1][0]);
            mma_f16(oacc[1], ph, &bv[1][2]);
            mma_f16(oacc[0], pl, &bv[0][0]);
            mma_f16(oacc[1], pl, &bv[0][2]);
        }
        __syncthreads();
        if (kt + 2 < 8) vfill(kt + 2, kt & 1);
    }

    // ---- write O split directly (ctx h/l) ----
    {
        int orow = b * SEQ + q0 + pr0;
        int ocol = h * DKH + nq * 16 + pc0;
#pragma unroll
        for (int nt = 0; nt < 2; nt++) {
            float dummy;
            ushort2 s0 = split_h(oacc[nt][0], dummy), s1 = split_h(oacc[nt][1], dummy);
            ushort2 s2 = split_h(oacc[nt][2], dummy), s3 = split_h(oacc[nt][3], dummy);
            *(ushort2*)&C0[(size_t)orow * D_MODEL + ocol + nt * 8]       = make_ushort2(s0.x, s1.x);
            *(ushort2*)&C1[(size_t)orow * D_MODEL + ocol + nt * 8]       = make_ushort2(s0.y, s1.y);
            *(ushort2*)&C0[(size_t)(orow + 8) * D_MODEL + ocol + nt * 8] = make_ushort2(s2.x, s3.x);
            *(ushort2*)&C1[(size_t)(orow + 8) * D_MODEL + ocol + nt * 8] = make_ushort2(s2.y, s3.y);
        }
    }
}

// =================================================================================
// Residual add + LayerNorm
// =================================================================================
__global__ __launch_bounds__(256) void ln_kernel(
    const float* __restrict__ fc, const float* __restrict__ resid,
    const float* __restrict__ gamma, const float* __restrict__ beta,
    float* __restrict__ out)
{
    __shared__ float xs[D_MODEL];
    __shared__ float rs[8], rss[8];

    const int row = blockIdx.x;
    const int t   = threadIdx.x;
    const float* f = fc    + (size_t)row * D_MODEL;
    const float* r = resid + (size_t)row * D_MODEL;

    float s = 0.f, ss = 0.f;
    for (int i = t; i < D_MODEL; i += 256) {
        float x = f[i] + r[i];
        xs[i] = x;
        s += x; ss += x * x;
    }
#pragma unroll
    for (int o = 16; o > 0; o >>= 1) {
        s  += __shfl_xor_sync(0xffffffffu, s, o);
        ss += __shfl_xor_sync(0xffffffffu, ss, o);
    }
    int w = t >> 5, lane = t & 31;
    if (lane == 0) { rs[w] = s; rss[w] = ss; }
    __syncthreads();
    float ts = 0.f, tss = 0.f;
#pragma unroll
    for (int i = 0; i < 8; i++) { ts += rs[i]; tss += rss[i]; }
    float mu  = ts * (1.0f / D_MODEL);
    float var = tss * (1.0f / D_MODEL) - mu * mu;
    float kk  = rsqrtf(var + 1e-5f);

    for (int i = t; i < D_MODEL; i += 256)
        out[(size_t)row * D_MODEL + i] = (xs[i] - mu) * kk * gamma[i] + beta[i];
}

// =================================================================================
// launch
// =================================================================================
extern "C" void kernel_launch(void* const* d_in, const int* in_sizes, int n_in,
                              void* d_out, int out_size)
{
    const float* q    = (const float*)d_in[0];
    const float* k    = (const float*)d_in[1];
    const float* v    = (const float*)d_in[2];
    const unsigned char* mask = (const unsigned char*)d_in[3];
    const float* w_q  = (const float*)d_in[4];
    const float* b_q  = (const float*)d_in[5];
    const float* w_k  = (const float*)d_in[6];
    const float* b_k  = (const float*)d_in[7];
    const float* w_v  = (const float*)d_in[8];
    const float* b_v  = (const float*)d_in[9];
    const float* w_fc = (const float*)d_in[10];
    const float* b_fc = (const float*)d_in[11];
    const float* ln_g = (const float*)d_in[12];
    const float* ln_b = (const float*)d_in[13];
    float* out = (float*)d_out;

    float *qh, *vh, *ctx, *fc;
    unsigned short *a0, *a1, *b0, *b1, *k0s, *k1s;
    cudaGetSymbolAddress((void**)&qh,  g_qh);
    cudaGetSymbolAddress((void**)&vh,  g_vh);
    cudaGetSymbolAddress((void**)&ctx, g_ctx);
    cudaGetSymbolAddress((void**)&fc,  g_fc);
    cudaGetSymbolAddress((void**)&a0,  g_a0);
    cudaGetSymbolAddress((void**)&a1,  g_a1);
    cudaGetSymbolAddress((void**)&b0,  g_b0);
    cudaGetSymbolAddress((void**)&b1,  g_b1);
    cudaGetSymbolAddress((void**)&k0s, g_k0s);
    cudaGetSymbolAddress((void**)&k1s, g_k1s);

    // carve split buffers out of the fp32 scratch
    unsigned short* q0s = (unsigned short*)qh;
    unsigned short* q1s = q0s + (size_t)MROWS * D_MODEL;
    unsigned short* c0s = (unsigned short*)ctx;
    unsigned short* c1s = c0s + (size_t)MROWS * D_MODEL;

    const long long xe = (long long)MROWS * D_MODEL;
    const long long ae = (long long)BATCH * NHEAD * SEQ * SEQ;
    float* attn_out = nullptr;
    float* x_out    = out;
    if ((long long)out_size >= xe + ae) {
        attn_out = out + xe;
    } else if ((long long)out_size == ae) {
        attn_out = out;
        x_out = nullptr;
    }

    cudaFuncSetAttribute((void*)gemm_2h<3, true>,  cudaFuncAttributeMaxDynamicSharedMemorySize, GSMEM3);
    cudaFuncSetAttribute((void*)gemm_2h<3, false>, cudaFuncAttributeMaxDynamicSharedMemorySize, GSMEM3);
    cudaFuncSetAttribute((void*)attn_mma, cudaFuncAttributeMaxDynamicSharedMemorySize, ATTN_SMEM);

    const int nA4 = MROWS * D_MODEL / 4;
    const int nW4 = D_MODEL * D_MODEL / 4;
    dim3 gb(256);
    dim3 gg(D_MODEL / 64, MROWS / 128);    // (16, 64)

    // Q projection -> split output directly (3-pass: 2^-22)
    split2h_kernel<<<nA4 / 256, gb>>>(q, a0, a1, nA4);
    split2h_kernel<<<nW4 / 256, gb>>>(w_q, b0, b1, nW4);
    gemm_2h<3, true><<<gg, gb, GSMEM3>>>(a0, a1, b0, b1, b_q, nullptr, q0s, q1s);

    // K projection -> split output directly (3-pass)
    split2h_kernel<<<nA4 / 256, gb>>>(k, a0, a1, nA4);
    split2h_kernel<<<nW4 / 256, gb>>>(w_k, b0, b1, nW4);
    gemm_2h<3, true><<<gg, gb, GSMEM3>>>(a0, a1, b0, b1, b_k, nullptr, k0s, k1s);

    // V projection -> fp32 (vtrans consumes it)
    split2h_kernel<<<nA4 / 256, gb>>>(v, a0, a1, nA4);
    split2h_kernel<<<nW4 / 256, gb>>>(w_v, b0, b1, nW4);
    gemm_2h<3, false><<<gg, gb, GSMEM3>>>(a0, a1, b0, b1, b_v, vh, nullptr, nullptr);

    vtrans_kernel<<<dim3(SEQ / 32, DKH / 32, BATCH * NHEAD), dim3(32, 8)>>>();

    dim3 ag(SEQ / 32, NHEAD, BATCH);
    attn_mma<<<ag, gb, ATTN_SMEM>>>(mask, attn_out, q0s, q1s, c0s, c1s);

    // FC (ctx split produced by attention epilogue)
    split2h_kernel<<<nW4 / 256, gb>>>(w_fc, b0, b1, nW4);
    gemm_2h<3, false><<<gg, gb, GSMEM3>>>(c0s, c1s, b0, b1, b_fc, fc, nullptr, nullptr);

    if (x_out)
        ln_kernel<<<MROWS, gb>>>(fc, q, ln_g, ln_b, x_out);
}